// round 8
// baseline (speedup 1.0000x reference)
#include <cuda_runtime.h>
#include <cuda_bf16.h>
#include <cstdint>
#include <math.h>

#define BB   2
#define SS   4096
#define DIM  1024
#define AD   1024
#define QKV3 (3*AD)

// ---------------------------------------------------------------------------
// Device scratch (no dynamic allocation allowed)
// ---------------------------------------------------------------------------
__device__ __nv_bfloat16 g_xh[(size_t)BB*SS*DIM];    // x hi
__device__ __nv_bfloat16 g_xl[(size_t)BB*SS*DIM];    // x lo
__device__ __nv_bfloat16 g_wh[(size_t)QKV3*DIM];     // W hi
__device__ __nv_bfloat16 g_wl[(size_t)QKV3*DIM];     // W lo
__device__ __nv_bfloat16 g_qh[(size_t)BB*SS*AD];     // Q hi
__device__ __nv_bfloat16 g_ql[(size_t)BB*SS*AD];
__device__ __nv_bfloat16 g_kh[(size_t)BB*SS*AD];     // K hi
__device__ __nv_bfloat16 g_kl[(size_t)BB*SS*AD];
__device__ float         g_v [(size_t)BB*SS*AD];     // V fp32
__device__ __nv_bfloat16 g_vth[(size_t)BB*AD*SS];    // V^T hi  [B,AD,S]
__device__ __nv_bfloat16 g_vtl[(size_t)BB*AD*SS];
__device__ __nv_bfloat16 g_ph[(size_t)BB*SS*SS];     // unnormalized exp hi
__device__ __nv_bfloat16 g_pl[(size_t)BB*SS*SS];     // unnormalized exp lo

// ---------------------------------------------------------------------------
// PTX helpers (compute_103-safe: cp.async + ldmatrix + mma.sync only)
// ---------------------------------------------------------------------------
static __device__ __forceinline__ uint32_t smem_u32(const void* p) {
    uint32_t a;
    asm("{ .reg .u64 t; cvta.to.shared.u64 t, %1; cvt.u32.u64 %0, t; }" : "=r"(a) : "l"(p));
    return a;
}
#define CP_ASYNC16(dst, src) \
    asm volatile("cp.async.cg.shared.global [%0], [%1], 16;" :: "r"(dst), "l"(src))
#define CP_COMMIT() asm volatile("cp.async.commit_group;" ::: "memory")
#define CP_WAIT(n)  asm volatile("cp.async.wait_group %0;" :: "n"(n) : "memory")

static __device__ __forceinline__ void ldsm4(uint32_t& r0, uint32_t& r1, uint32_t& r2, uint32_t& r3, uint32_t addr) {
    asm volatile("ldmatrix.sync.aligned.m8n8.x4.shared.b16 {%0,%1,%2,%3}, [%4];"
                 : "=r"(r0), "=r"(r1), "=r"(r2), "=r"(r3) : "r"(addr));
}
static __device__ __forceinline__ void mma16816(float* c,
                                                uint32_t a0, uint32_t a1, uint32_t a2, uint32_t a3,
                                                uint32_t b0, uint32_t b1) {
    asm volatile("mma.sync.aligned.m16n8k16.row.col.f32.bf16.bf16.f32 "
                 "{%0,%1,%2,%3}, {%4,%5,%6,%7}, {%8,%9}, {%0,%1,%2,%3};"
                 : "+f"(c[0]), "+f"(c[1]), "+f"(c[2]), "+f"(c[3])
                 : "r"(a0), "r"(a1), "r"(a2), "r"(a3), "r"(b0), "r"(b1));
}

static __device__ __forceinline__ void store_split2(__nv_bfloat16* H, __nv_bfloat16* L,
                                                    size_t idx, float v0, float v1) {
    __nv_bfloat162 h = __floats2bfloat162_rn(v0, v1);
    __nv_bfloat162 l = __floats2bfloat162_rn(v0 - __bfloat162float(h.x),
                                             v1 - __bfloat162float(h.y));
    *(__nv_bfloat162*)(H + idx) = h;
    *(__nv_bfloat162*)(L + idx) = l;
}

// ---------------------------------------------------------------------------
// HMMA core: C[128x128] += A[128xK] * B[128xK]^T, bf16x3 emulation.
// 128 threads (4 warps), each warp owns a 64x64 sub-tile -> 96 MMA : 16 LDSM
// per k16 (ratio 6). 2-stage cp.async pipeline, 82KB smem -> 2 CTAs/SM so the
// co-resident CTA covers this CTA's sync/load bubbles.
// smem stage: Ah Al Bh Bl, 128 rows x 80B each (64B data + 16B pad).
// ---------------------------------------------------------------------------
#define T_BYTES    10240           // 128 rows * 80B
#define STAGE_B    (4*T_BYTES)     // 40960
#define SMEM_TOTAL (2*STAGE_B)     // 81920

static __device__ __forceinline__ void stage_tile(uint32_t sdst, const __nv_bfloat16* src,
                                                  int ld, int tid) {
    #pragma unroll
    for (int i = 0; i < 4; ++i) {
        int ci = tid * 4 + i;              // 0..511
        int r = ci >> 2, c = ci & 3;
        CP_ASYNC16(sdst + r * 80 + c * 16, (const char*)(src + (size_t)r * ld) + c * 16);
    }
}

template<bool RS>
static __device__ __forceinline__ void gemm128(
    const __nv_bfloat16* __restrict__ Ah, const __nv_bfloat16* __restrict__ Al, int lda,
    const __nv_bfloat16* __restrict__ Bh, const __nv_bfloat16* __restrict__ Bl, int ldb,
    int nChunks, char* smem, float acc[32][4], float rsacc[4][4])
{
    const int tid  = threadIdx.x;
    const int lane = tid & 31;
    const int w    = tid >> 5;            // 0..3
    const int m_off = (w >> 1) * 64;
    const int n_off = (w & 1) * 64;
    uint32_t sb = smem_u32(smem);
    const uint32_t ONE2 = 0x3F803F80u;     // packed bf16 {1.0, 1.0}

    // ldmatrix lane-address components
    const uint32_t a_row  = (uint32_t)(lane & 15);
    const uint32_t a_koff = (uint32_t)((lane >> 4) & 1) * 16;
    const uint32_t b_row  = (uint32_t)(((lane >> 4) << 3) + (lane & 7));
    const uint32_t b_koff = (uint32_t)((lane >> 3) & 1) * 16;

    // prefetch stage 0
    {
        uint32_t st = sb;
        stage_tile(st,             Ah, lda, tid);
        stage_tile(st + T_BYTES,   Al, lda, tid);
        stage_tile(st + 2*T_BYTES, Bh, ldb, tid);
        stage_tile(st + 3*T_BYTES, Bl, ldb, tid);
        CP_COMMIT();
    }

    for (int i = 0; i < nChunks; ++i) {
        if (i + 1 < nChunks) {
            uint32_t st = sb + ((i + 1) & 1) * STAGE_B;
            stage_tile(st,             Ah + (size_t)(i + 1) * 32, lda, tid);
            stage_tile(st + T_BYTES,   Al + (size_t)(i + 1) * 32, lda, tid);
            stage_tile(st + 2*T_BYTES, Bh + (size_t)(i + 1) * 32, ldb, tid);
            stage_tile(st + 3*T_BYTES, Bl + (size_t)(i + 1) * 32, ldb, tid);
            CP_COMMIT();
            CP_WAIT(1);
        } else {
            CP_WAIT(0);
        }
        __syncthreads();

        uint32_t st = sb + (i & 1) * STAGE_B;
        #pragma unroll
        for (int k16 = 0; k16 < 2; ++k16) {
            uint32_t kb = k16 * 32;       // 16 bf16 = 32 bytes
            uint32_t bh[16], bl[16];
            #pragma unroll
            for (int h = 0; h < 4; ++h) {
                uint32_t addr = st + 2*T_BYTES + (uint32_t)(n_off + h*16 + b_row) * 80 + kb + b_koff;
                ldsm4(bh[h*4], bh[h*4+1], bh[h*4+2], bh[h*4+3], addr);
                ldsm4(bl[h*4], bl[h*4+1], bl[h*4+2], bl[h*4+3], addr + T_BYTES);
            }
            #pragma unroll
            for (int mf = 0; mf < 4; ++mf) {
                uint32_t addr = st + (uint32_t)(m_off + mf*16 + a_row) * 80 + kb + a_koff;
                uint32_t h0, h1, h2, h3, l0, l1, l2, l3;
                ldsm4(h0, h1, h2, h3, addr);
                ldsm4(l0, l1, l2, l3, addr + T_BYTES);
                if (RS) {
                    mma16816(rsacc[mf], h0, h1, h2, h3, ONE2, ONE2);   // Σ Ah
                    mma16816(rsacc[mf], l0, l1, l2, l3, ONE2, ONE2);   // Σ Al
                }
                #pragma unroll
                for (int nf = 0; nf < 8; ++nf) {
                    float* c = acc[mf*8 + nf];
                    uint32_t B0 = bh[nf*2], B1 = bh[nf*2+1];
                    mma16816(c, h0, h1, h2, h3, B0, B1);               // Ah*Bh
                    mma16816(c, h0, h1, h2, h3, bl[nf*2], bl[nf*2+1]); // Ah*Bl
                    mma16816(c, l0, l1, l2, l3, B0, B1);               // Al*Bh
                }
            }
        }
        __syncthreads();
    }
}

// ---------------------------------------------------------------------------
// Split kernels: fp32 -> bf16 hi/lo (device globals referenced in device code)
// ---------------------------------------------------------------------------
__global__ void __launch_bounds__(256) split_x_kernel(const float* __restrict__ s) {
    int i = (blockIdx.x * 256 + threadIdx.x) * 4;
    float4 v = *(const float4*)(s + i);
    store_split2(g_xh, g_xl, i,     v.x, v.y);
    store_split2(g_xh, g_xl, i + 2, v.z, v.w);
}
__global__ void __launch_bounds__(256) split_w_kernel(const float* __restrict__ s) {
    int i = (blockIdx.x * 256 + threadIdx.x) * 4;
    float4 v = *(const float4*)(s + i);
    store_split2(g_wh, g_wl, i,     v.x, v.y);
    store_split2(g_wh, g_wl, i + 2, v.z, v.w);
}

// ---------------------------------------------------------------------------
// QKV GEMM: [8192,3072] = x @ W^T + bias; route N-segments to Q/K split, V fp32
// ---------------------------------------------------------------------------
__global__ void __launch_bounds__(128, 2) qkv_mma(const float* __restrict__ bias) {
    extern __shared__ __align__(128) char sm[];
    const int m0 = blockIdx.y * 128, n0 = blockIdx.x * 128;
    const int lane = threadIdx.x & 31, w = threadIdx.x >> 5;
    const int m_off = (w >> 1) * 64, n_off = (w & 1) * 64;

    float acc[32][4];
    #pragma unroll
    for (int i = 0; i < 32; ++i)
        #pragma unroll
        for (int j = 0; j < 4; ++j) acc[i][j] = 0.0f;
    float rs_dummy[4][4];

    gemm128<false>(g_xh + (size_t)m0 * DIM, g_xl + (size_t)m0 * DIM, DIM,
                   g_wh + (size_t)n0 * DIM, g_wl + (size_t)n0 * DIM, DIM,
                   DIM / 32, sm, acc, rs_dummy);

    #pragma unroll
    for (int mf = 0; mf < 4; ++mf) {
        #pragma unroll
        for (int nf = 0; nf < 8; ++nf) {
            float* c = acc[mf*8 + nf];
            int r  = m0 + m_off + mf*16 + (lane >> 2);
            int cg = n0 + n_off + nf*8 + ((lane & 3) << 1);
            float b0 = bias[cg], b1 = bias[cg + 1];
            float v0 = c[0] + b0, v1 = c[1] + b1;     // row r
            float v2 = c[2] + b0, v3 = c[3] + b1;     // row r+8
            if (cg < AD) {
                store_split2(g_qh, g_ql, (size_t)r * AD + cg,       v0, v1);
                store_split2(g_qh, g_ql, (size_t)(r + 8) * AD + cg, v2, v3);
            } else if (cg < 2*AD) {
                int ck = cg - AD;
                store_split2(g_kh, g_kl, (size_t)r * AD + ck,       v0, v1);
                store_split2(g_kh, g_kl, (size_t)(r + 8) * AD + ck, v2, v3);
            } else {
                int cv = cg - 2*AD;
                *(float2*)(g_v + (size_t)r * AD + cv)       = make_float2(v0, v1);
                *(float2*)(g_v + (size_t)(r + 8) * AD + cv) = make_float2(v2, v3);
            }
        }
    }
}

// ---------------------------------------------------------------------------
// V transpose + split: g_v [B,S,AD] -> g_vth/g_vtl [B,AD,S]
// ---------------------------------------------------------------------------
__global__ void __launch_bounds__(256) vt_split_kernel() {
    __shared__ float t[32][33];
    const int b = blockIdx.z;
    const int k0 = blockIdx.x * 32, n0 = blockIdx.y * 32;
    const int tx = threadIdx.x, ty = threadIdx.y;     // 32 x 8
    const float* V = g_v + (size_t)b * SS * AD;
    #pragma unroll
    for (int j = 0; j < 4; ++j)
        t[ty + j * 8][tx] = V[(size_t)(k0 + ty + j * 8) * AD + n0 + tx];
    __syncthreads();
    #pragma unroll
    for (int j = 0; j < 4; ++j) {
        int n = n0 + ty + j * 8;
        int k = k0 + tx;
        float v = t[tx][ty + j * 8];
        __nv_bfloat16 h = __float2bfloat16(v);
        __nv_bfloat16 l = __float2bfloat16(v - __bfloat162float(h));
        size_t idx = ((size_t)b * AD + n) * SS + k;
        g_vth[idx] = h;
        g_vtl[idx] = l;
    }
}

// ---------------------------------------------------------------------------
// Scores GEMM + fused exp: writes UNNORMALIZED e = exp(s/32) as bf16 hi/lo.
// No max subtraction needed: s/32 ~ N(0,1), fp32 exp overflow far away.
// Diagonal blocks mask j>i to exactly 0 (matches -inf-before-scale reference).
// ---------------------------------------------------------------------------
__global__ void __launch_bounds__(128, 2) scores_mma() {
    const int bx = blockIdx.x, by = blockIdx.y, b = blockIdx.z;
    if (bx > by) return;
    extern __shared__ __align__(128) char sm[];
    const int m0 = by * 128, n0 = bx * 128;
    const int lane = threadIdx.x & 31, w = threadIdx.x >> 5;
    const int m_off = (w >> 1) * 64, n_off = (w & 1) * 64;

    float acc[32][4];
    #pragma unroll
    for (int i = 0; i < 32; ++i)
        #pragma unroll
        for (int j = 0; j < 4; ++j) acc[i][j] = 0.0f;
    float rs_dummy[4][4];

    const size_t qo = ((size_t)b * SS + m0) * AD;
    const size_t ko = ((size_t)b * SS + n0) * AD;
    gemm128<false>(g_qh + qo, g_ql + qo, AD, g_kh + ko, g_kl + ko, AD,
                   AD / 32, sm, acc, rs_dummy);

    __nv_bfloat16* ph = g_ph + (size_t)b * SS * SS;
    __nv_bfloat16* pl = g_pl + (size_t)b * SS * SS;
    const float inv = 1.0f / 32.0f;
    const bool diag = (bx == by);
    #pragma unroll
    for (int mf = 0; mf < 4; ++mf) {
        #pragma unroll
        for (int nf = 0; nf < 8; ++nf) {
            float* c = acc[mf*8 + nf];
            int r  = m0 + m_off + mf*16 + (lane >> 2);
            int cg = n0 + n_off + nf*8 + ((lane & 3) << 1);
            float e0 = expf(c[0] * inv), e1 = expf(c[1] * inv);
            float e2 = expf(c[2] * inv), e3 = expf(c[3] * inv);
            if (diag) {
                if (cg     > r)     e0 = 0.0f;
                if (cg + 1 > r)     e1 = 0.0f;
                if (cg     > r + 8) e2 = 0.0f;
                if (cg + 1 > r + 8) e3 = 0.0f;
            }
            store_split2(ph, pl, (size_t)r * SS + cg,       e0, e1);
            store_split2(ph, pl, (size_t)(r + 8) * SS + cg, e2, e3);
        }
    }
}

// ---------------------------------------------------------------------------
// PV GEMM: y = (E @ V) / rowsum(E), K truncated at causal boundary.
// Row sums via ones-vector MMA inside the mainloop (deterministic, free pass).
// ---------------------------------------------------------------------------
__global__ void __launch_bounds__(128, 2) pv_mma(float* __restrict__ y) {
    extern __shared__ __align__(128) char sm[];
    const int b = blockIdx.z;
    const int m0 = blockIdx.y * 128, n0 = blockIdx.x * 128;
    const int lane = threadIdx.x & 31, w = threadIdx.x >> 5;
    const int m_off = (w >> 1) * 64, n_off = (w & 1) * 64;

    float acc[32][4];
    #pragma unroll
    for (int i = 0; i < 32; ++i)
        #pragma unroll
        for (int j = 0; j < 4; ++j) acc[i][j] = 0.0f;
    float rs[4][4];
    #pragma unroll
    for (int i = 0; i < 4; ++i)
        #pragma unroll
        for (int j = 0; j < 4; ++j) rs[i][j] = 0.0f;

    const size_t po = ((size_t)b * SS + m0) * SS;
    const size_t vo = ((size_t)b * AD + n0) * SS;
    gemm128<true>(g_ph + po, g_pl + po, SS, g_vth + vo, g_vtl + vo, SS,
                  (blockIdx.y + 1) * 4, sm, acc, rs);

    #pragma unroll
    for (int mf = 0; mf < 4; ++mf) {
        const float i0 = 1.0f / rs[mf][0];     // row r   sum
        const float i1 = 1.0f / rs[mf][2];     // row r+8 sum
        #pragma unroll
        for (int nf = 0; nf < 8; ++nf) {
            float* c = acc[mf*8 + nf];
            int r  = m0 + m_off + mf*16 + (lane >> 2);
            int cg = n0 + n_off + nf*8 + ((lane & 3) << 1);
            *(float2*)(y + ((size_t)b * SS + r) * AD + cg)     = make_float2(c[0] * i0, c[1] * i0);
            *(float2*)(y + ((size_t)b * SS + r + 8) * AD + cg) = make_float2(c[2] * i1, c[3] * i1);
        }
    }
}

// ---------------------------------------------------------------------------
extern "C" void kernel_launch(void* const* d_in, const int* in_sizes, int n_in,
                              void* d_out, int out_size)
{
    const float* x    = (const float*)d_in[0];   // [B,S,DIM]
    const float* W    = (const float*)d_in[1];   // [3*AD, DIM]
    const float* bias = (const float*)d_in[2];   // [3*AD]
    float* y = (float*)d_out;                    // [B,S,AD]

    cudaFuncSetAttribute(qkv_mma,    cudaFuncAttributeMaxDynamicSharedMemorySize, SMEM_TOTAL);
    cudaFuncSetAttribute(scores_mma, cudaFuncAttributeMaxDynamicSharedMemorySize, SMEM_TOTAL);
    cudaFuncSetAttribute(pv_mma,     cudaFuncAttributeMaxDynamicSharedMemorySize, SMEM_TOTAL);

    split_x_kernel<<<(BB*SS*DIM) / 1024, 256>>>(x);
    split_w_kernel<<<(QKV3*DIM) / 1024, 256>>>(W);
    qkv_mma   <<<dim3(QKV3/128, (BB*SS)/128), 128, SMEM_TOTAL>>>(bias);
    vt_split_kernel<<<dim3(SS/32, AD/32, BB), dim3(32, 8)>>>();
    scores_mma<<<dim3(SS/128, SS/128, BB), 128, SMEM_TOTAL>>>();
    pv_mma    <<<dim3(AD/128, SS/128, BB), 128, SMEM_TOTAL>>>(y);
}

// round 11
// speedup vs baseline: 1.5460x; 1.5460x over previous
#include <cuda_runtime.h>
#include <cuda_fp16.h>
#include <cstdint>
#include <math.h>

#define BB   2
#define SS   4096
#define DIM  1024
#define AD   1024
#define QKV3 (3*AD)

// ---------------------------------------------------------------------------
// Device scratch. Asymmetric fp16 scheme: A-side operands stored single fp16,
// B-side operands stored as hi/lo fp16 pair.
// ---------------------------------------------------------------------------
__device__ __half g_xa [(size_t)BB*SS*DIM];    // x   (A-side, single)
__device__ __half g_wh [(size_t)QKV3*DIM];     // W hi (B-side)
__device__ __half g_wl [(size_t)QKV3*DIM];     // W lo
__device__ __half g_qa [(size_t)BB*SS*AD];     // Q   (A-side, single)
__device__ __half g_kh [(size_t)BB*SS*AD];     // K hi (B-side)
__device__ __half g_kl [(size_t)BB*SS*AD];
__device__ float  g_v  [(size_t)BB*SS*AD];     // V fp32 (pre-transpose)
__device__ __half g_vth[(size_t)BB*AD*SS];     // V^T hi (B-side) [B,AD,S]
__device__ __half g_vtl[(size_t)BB*AD*SS];
__device__ __half g_pa [(size_t)BB*SS*SS];     // unnormalized exp(s/32) (A-side)

// ---------------------------------------------------------------------------
// PTX helpers (compute_103-safe: cp.async + ldmatrix + mma.sync only)
// ---------------------------------------------------------------------------
static __device__ __forceinline__ uint32_t smem_u32(const void* p) {
    uint32_t a;
    asm("{ .reg .u64 t; cvta.to.shared.u64 t, %1; cvt.u32.u64 %0, t; }" : "=r"(a) : "l"(p));
    return a;
}
#define CP_ASYNC16(dst, src) \
    asm volatile("cp.async.cg.shared.global [%0], [%1], 16;" :: "r"(dst), "l"(src))
#define CP_COMMIT() asm volatile("cp.async.commit_group;" ::: "memory")
#define CP_WAIT(n)  asm volatile("cp.async.wait_group %0;" :: "n"(n) : "memory")

static __device__ __forceinline__ void ldsm4(uint32_t& r0, uint32_t& r1, uint32_t& r2, uint32_t& r3, uint32_t addr) {
    asm volatile("ldmatrix.sync.aligned.m8n8.x4.shared.b16 {%0,%1,%2,%3}, [%4];"
                 : "=r"(r0), "=r"(r1), "=r"(r2), "=r"(r3) : "r"(addr));
}
static __device__ __forceinline__ void mma16816(float* c,
                                                uint32_t a0, uint32_t a1, uint32_t a2, uint32_t a3,
                                                uint32_t b0, uint32_t b1) {
    asm volatile("mma.sync.aligned.m16n8k16.row.col.f32.f16.f16.f32 "
                 "{%0,%1,%2,%3}, {%4,%5,%6,%7}, {%8,%9}, {%0,%1,%2,%3};"
                 : "+f"(c[0]), "+f"(c[1]), "+f"(c[2]), "+f"(c[3])
                 : "r"(a0), "r"(a1), "r"(a2), "r"(a3), "r"(b0), "r"(b1));
}

// fp16 hi/lo split store (B-side operands)
static __device__ __forceinline__ void store_split2h(__half* H, __half* L,
                                                     size_t idx, float v0, float v1) {
    __half h0 = __float2half_rn(v0), h1 = __float2half_rn(v1);
    __half l0 = __float2half_rn(v0 - __half2float(h0));
    __half l1 = __float2half_rn(v1 - __half2float(h1));
    *(__half2*)(H + idx) = __halves2half2(h0, h1);
    *(__half2*)(L + idx) = __halves2half2(l0, l1);
}
static __device__ __forceinline__ void store_h2(__half* H, size_t idx, float v0, float v1) {
    *(__half2*)(H + idx) = __halves2half2(__float2half_rn(v0), __float2half_rn(v1));
}

// ---------------------------------------------------------------------------
// HMMA core: C[128x128] += A[128xK] * B[128xK]^T, asymmetric fp16 2-term:
//   C = A*Bh + A*Bl        (A single fp16; dropped A_lo term ~ 2^-11 rel)
// 256 threads, 8 warps, warp tile 64x32. 2-stage cp.async pipeline.
// smem stage: A, Bh, Bl — 128 rows x 80B each (64B data + 16B pad).
// Optional RS: row sums of A via ones-vector MMA (PV normalization).
// ---------------------------------------------------------------------------
#define T_BYTES    10240           // 128 rows * 80B
#define STAGE_B    (3*T_BYTES)     // 30720
#define SMEM_TOTAL (2*STAGE_B)     // 61440

static __device__ __forceinline__ void stage_tile(uint32_t sdst, const __half* src,
                                                  int ld, int tid) {
    #pragma unroll
    for (int i = 0; i < 2; ++i) {
        int ci = tid * 2 + i;              // 0..511
        int r = ci >> 2, c = ci & 3;
        CP_ASYNC16(sdst + r * 80 + c * 16, (const char*)(src + (size_t)r * ld) + c * 16);
    }
}

template<bool RS>
static __device__ __forceinline__ void gemm128(
    const __half* __restrict__ A, int lda,
    const __half* __restrict__ Bh, const __half* __restrict__ Bl, int ldb,
    int nChunks, char* smem, float acc[16][4], float rsacc[4][4])
{
    const int tid  = threadIdx.x;
    const int lane = tid & 31;
    const int w    = tid >> 5;
    const int m_off = (w >> 2) * 64;
    const int n_off = (w & 3) * 32;
    uint32_t sb = smem_u32(smem);
    const uint32_t ONE2 = 0x3C003C00u;     // packed fp16 {1.0, 1.0}

    // ldmatrix lane-address components
    const uint32_t a_row  = (uint32_t)(lane & 15);
    const uint32_t a_koff = (uint32_t)((lane >> 4) & 1) * 16;
    const uint32_t b_row  = (uint32_t)(((lane >> 4) << 3) + (lane & 7));
    const uint32_t b_koff = (uint32_t)((lane >> 3) & 1) * 16;

    // prefetch stage 0
    {
        uint32_t st = sb;
        stage_tile(st,             A,  lda, tid);
        stage_tile(st + T_BYTES,   Bh, ldb, tid);
        stage_tile(st + 2*T_BYTES, Bl, ldb, tid);
        CP_COMMIT();
    }

    for (int i = 0; i < nChunks; ++i) {
        if (i + 1 < nChunks) {
            uint32_t st = sb + ((i + 1) & 1) * STAGE_B;
            stage_tile(st,             A  + (size_t)(i + 1) * 32, lda, tid);
            stage_tile(st + T_BYTES,   Bh + (size_t)(i + 1) * 32, ldb, tid);
            stage_tile(st + 2*T_BYTES, Bl + (size_t)(i + 1) * 32, ldb, tid);
            CP_COMMIT();
            CP_WAIT(1);
        } else {
            CP_WAIT(0);
        }
        __syncthreads();

        uint32_t st = sb + (i & 1) * STAGE_B;
        #pragma unroll
        for (int k16 = 0; k16 < 2; ++k16) {
            uint32_t kb = k16 * 32;       // 16 fp16 = 32 bytes
            uint32_t bh[8], bl[8];
            #pragma unroll
            for (int h = 0; h < 2; ++h) {
                uint32_t addr = st + T_BYTES + (uint32_t)(n_off + h*16 + b_row) * 80 + kb + b_koff;
                ldsm4(bh[h*4], bh[h*4+1], bh[h*4+2], bh[h*4+3], addr);
                ldsm4(bl[h*4], bl[h*4+1], bl[h*4+2], bl[h*4+3], addr + T_BYTES);
            }
            #pragma unroll
            for (int mf = 0; mf < 4; ++mf) {
                uint32_t addr = st + (uint32_t)(m_off + mf*16 + a_row) * 80 + kb + a_koff;
                uint32_t a0, a1, a2, a3;
                ldsm4(a0, a1, a2, a3, addr);
                if (RS) {
                    mma16816(rsacc[mf], a0, a1, a2, a3, ONE2, ONE2);   // Σ A
                }
                #pragma unroll
                for (int nf = 0; nf < 4; ++nf) {
                    float* c = acc[mf*4 + nf];
                    mma16816(c, a0, a1, a2, a3, bh[nf*2], bh[nf*2+1]); // A*Bh
                    mma16816(c, a0, a1, a2, a3, bl[nf*2], bl[nf*2+1]); // A*Bl
                }
            }
        }
        __syncthreads();
    }
}

// ---------------------------------------------------------------------------
// Split kernels (device globals referenced in device code only)
// ---------------------------------------------------------------------------
__global__ void __launch_bounds__(256) split_x_kernel(const float* __restrict__ s) {
    int i = (blockIdx.x * 256 + threadIdx.x) * 4;
    float4 v = *(const float4*)(s + i);
    store_h2(g_xa, i,     v.x, v.y);
    store_h2(g_xa, i + 2, v.z, v.w);
}
__global__ void __launch_bounds__(256) split_w_kernel(const float* __restrict__ s) {
    int i = (blockIdx.x * 256 + threadIdx.x) * 4;
    float4 v = *(const float4*)(s + i);
    store_split2h(g_wh, g_wl, i,     v.x, v.y);
    store_split2h(g_wh, g_wl, i + 2, v.z, v.w);
}

// ---------------------------------------------------------------------------
// QKV GEMM: [8192,3072] = x @ W^T + bias.
// Epilogue routes: Q -> single fp16 (A-side), K -> fp16 hi/lo (B-side), V fp32.
// ---------------------------------------------------------------------------
__global__ void __launch_bounds__(256, 1) qkv_mma(const float* __restrict__ bias) {
    extern __shared__ __align__(128) char sm[];
    const int m0 = blockIdx.y * 128, n0 = blockIdx.x * 128;
    const int lane = threadIdx.x & 31, w = threadIdx.x >> 5;
    const int m_off = (w >> 2) * 64, n_off = (w & 3) * 32;

    float acc[16][4];
    #pragma unroll
    for (int i = 0; i < 16; ++i)
        #pragma unroll
        for (int j = 0; j < 4; ++j) acc[i][j] = 0.0f;
    float rs_dummy[4][4];

    gemm128<false>(g_xa + (size_t)m0 * DIM, DIM,
                   g_wh + (size_t)n0 * DIM, g_wl + (size_t)n0 * DIM, DIM,
                   DIM / 32, sm, acc, rs_dummy);

    #pragma unroll
    for (int mf = 0; mf < 4; ++mf) {
        #pragma unroll
        for (int nf = 0; nf < 4; ++nf) {
            float* c = acc[mf*4 + nf];
            int r  = m0 + m_off + mf*16 + (lane >> 2);
            int cg = n0 + n_off + nf*8 + ((lane & 3) << 1);
            float b0 = bias[cg], b1 = bias[cg + 1];
            float v0 = c[0] + b0, v1 = c[1] + b1;     // row r
            float v2 = c[2] + b0, v3 = c[3] + b1;     // row r+8
            if (cg < AD) {
                store_h2(g_qa, (size_t)r * AD + cg,       v0, v1);
                store_h2(g_qa, (size_t)(r + 8) * AD + cg, v2, v3);
            } else if (cg < 2*AD) {
                int ck = cg - AD;
                store_split2h(g_kh, g_kl, (size_t)r * AD + ck,       v0, v1);
                store_split2h(g_kh, g_kl, (size_t)(r + 8) * AD + ck, v2, v3);
            } else {
                int cv = cg - 2*AD;
                *(float2*)(g_v + (size_t)r * AD + cv)       = make_float2(v0, v1);
                *(float2*)(g_v + (size_t)(r + 8) * AD + cv) = make_float2(v2, v3);
            }
        }
    }
}

// ---------------------------------------------------------------------------
// V transpose + split: g_v [B,S,AD] -> g_vth/g_vtl [B,AD,S]  (B-side)
// ---------------------------------------------------------------------------
__global__ void __launch_bounds__(256) vt_split_kernel() {
    __shared__ float t[32][33];
    const int b = blockIdx.z;
    const int k0 = blockIdx.x * 32, n0 = blockIdx.y * 32;
    const int tx = threadIdx.x, ty = threadIdx.y;     // 32 x 8
    const float* V = g_v + (size_t)b * SS * AD;
    #pragma unroll
    for (int j = 0; j < 4; ++j)
        t[ty + j * 8][tx] = V[(size_t)(k0 + ty + j * 8) * AD + n0 + tx];
    __syncthreads();
    #pragma unroll
    for (int j = 0; j < 4; ++j) {
        int n = n0 + ty + j * 8;
        int k = k0 + tx;
        float v = t[tx][ty + j * 8];
        __half h = __float2half_rn(v);
        __half l = __float2half_rn(v - __half2float(h));
        size_t idx = ((size_t)b * AD + n) * SS + k;
        g_vth[idx] = h;
        g_vtl[idx] = l;
    }
}

// ---------------------------------------------------------------------------
// Scores GEMM + fused exp: writes UNNORMALIZED e = exp(s/32) as single fp16.
// s/32 ~ N(0,1); max |s|/32 ~ 5 -> e^5 = 148, comfortably inside fp16 range.
// Diagonal blocks mask j>i to exactly 0 (matches -inf-before-scale reference).
// ---------------------------------------------------------------------------
__global__ void __launch_bounds__(256, 1) scores_mma() {
    const int bx = blockIdx.x, by = blockIdx.y, b = blockIdx.z;
    if (bx > by) return;
    extern __shared__ __align__(128) char sm[];
    const int m0 = by * 128, n0 = bx * 128;
    const int lane = threadIdx.x & 31, w = threadIdx.x >> 5;
    const int m_off = (w >> 2) * 64, n_off = (w & 3) * 32;

    float acc[16][4];
    #pragma unroll
    for (int i = 0; i < 16; ++i)
        #pragma unroll
        for (int j = 0; j < 4; ++j) acc[i][j] = 0.0f;
    float rs_dummy[4][4];

    const size_t qo = ((size_t)b * SS + m0) * AD;
    const size_t ko = ((size_t)b * SS + n0) * AD;
    gemm128<false>(g_qa + qo, AD, g_kh + ko, g_kl + ko, AD,
                   AD / 32, sm, acc, rs_dummy);

    __half* pa = g_pa + (size_t)b * SS * SS;
    const float inv = 1.0f / 32.0f;
    const bool diag = (bx == by);
    #pragma unroll
    for (int mf = 0; mf < 4; ++mf) {
        #pragma unroll
        for (int nf = 0; nf < 4; ++nf) {
            float* c = acc[mf*4 + nf];
            int r  = m0 + m_off + mf*16 + (lane >> 2);
            int cg = n0 + n_off + nf*8 + ((lane & 3) << 1);
            float e0 = expf(c[0] * inv), e1 = expf(c[1] * inv);
            float e2 = expf(c[2] * inv), e3 = expf(c[3] * inv);
            if (diag) {
                if (cg     > r)     e0 = 0.0f;
                if (cg + 1 > r)     e1 = 0.0f;
                if (cg     > r + 8) e2 = 0.0f;
                if (cg + 1 > r + 8) e3 = 0.0f;
            }
            store_h2(pa, (size_t)r * SS + cg,       e0, e1);
            store_h2(pa, (size_t)(r + 8) * SS + cg, e2, e3);
        }
    }
}

// ---------------------------------------------------------------------------
// PV GEMM: y = (E @ V) / rowsum(E), K truncated at causal boundary.
// Row sums via ones-vector MMA on the SAME fp16 E used in the numerator.
// ---------------------------------------------------------------------------
__global__ void __launch_bounds__(256, 1) pv_mma(float* __restrict__ y) {
    extern __shared__ __align__(128) char sm[];
    const int b = blockIdx.z;
    const int m0 = blockIdx.y * 128, n0 = blockIdx.x * 128;
    const int lane = threadIdx.x & 31, w = threadIdx.x >> 5;
    const int m_off = (w >> 2) * 64, n_off = (w & 3) * 32;

    float acc[16][4];
    #pragma unroll
    for (int i = 0; i < 16; ++i)
        #pragma unroll
        for (int j = 0; j < 4; ++j) acc[i][j] = 0.0f;
    float rs[4][4];
    #pragma unroll
    for (int i = 0; i < 4; ++i)
        #pragma unroll
        for (int j = 0; j < 4; ++j) rs[i][j] = 0.0f;

    const size_t po = ((size_t)b * SS + m0) * SS;
    const size_t vo = ((size_t)b * AD + n0) * SS;
    gemm128<true>(g_pa + po, SS, g_vth + vo, g_vtl + vo, SS,
                  (blockIdx.y + 1) * 4, sm, acc, rs);

    #pragma unroll
    for (int mf = 0; mf < 4; ++mf) {
        const float i0 = 1.0f / rs[mf][0];     // row r   sum
        const float i1 = 1.0f / rs[mf][2];     // row r+8 sum
        #pragma unroll
        for (int nf = 0; nf < 4; ++nf) {
            float* c = acc[mf*4 + nf];
            int r  = m0 + m_off + mf*16 + (lane >> 2);
            int cg = n0 + n_off + nf*8 + ((lane & 3) << 1);
            *(float2*)(y + ((size_t)b * SS + r) * AD + cg)     = make_float2(c[0] * i0, c[1] * i0);
            *(float2*)(y + ((size_t)b * SS + r + 8) * AD + cg) = make_float2(c[2] * i1, c[3] * i1);
        }
    }
}

// ---------------------------------------------------------------------------
extern "C" void kernel_launch(void* const* d_in, const int* in_sizes, int n_in,
                              void* d_out, int out_size)
{
    const float* x    = (const float*)d_in[0];   // [B,S,DIM]
    const float* W    = (const float*)d_in[1];   // [3*AD, DIM]
    const float* bias = (const float*)d_in[2];   // [3*AD]
    float* y = (float*)d_out;                    // [B,S,AD]

    cudaFuncSetAttribute(qkv_mma,    cudaFuncAttributeMaxDynamicSharedMemorySize, SMEM_TOTAL);
    cudaFuncSetAttribute(scores_mma, cudaFuncAttributeMaxDynamicSharedMemorySize, SMEM_TOTAL);
    cudaFuncSetAttribute(pv_mma,     cudaFuncAttributeMaxDynamicSharedMemorySize, SMEM_TOTAL);

    split_x_kernel<<<(BB*SS*DIM) / 1024, 256>>>(x);
    split_w_kernel<<<(QKV3*DIM) / 1024, 256>>>(W);
    qkv_mma   <<<dim3(QKV3/128, (BB*SS)/128), 256, SMEM_TOTAL>>>(bias);
    vt_split_kernel<<<dim3(SS/32, AD/32, BB), dim3(32, 8)>>>();
    scores_mma<<<dim3(SS/128, SS/128, BB), 256, SMEM_TOTAL>>>();
    pv_mma    <<<dim3(AD/128, SS/128, BB), 256, SMEM_TOTAL>>>(y);
}

// round 12
// speedup vs baseline: 1.9202x; 1.2420x over previous
#include <cuda_runtime.h>
#include <cuda_fp16.h>
#include <cstdint>
#include <math.h>

#define BB   2
#define SS   4096
#define DIM  1024
#define AD   1024
#define QKV3 (3*AD)

// ---------------------------------------------------------------------------
// Device scratch. QKV GEMM: A=x single fp16, B=W hi/lo (2-term).
// Scores GEMM: A=Q single, B=K single (1-term). PV: A=P single, B=V^T single.
// ---------------------------------------------------------------------------
__device__ __half g_xa [(size_t)BB*SS*DIM];    // x   (single)
__device__ __half g_wh [(size_t)QKV3*DIM];     // W hi
__device__ __half g_wl [(size_t)QKV3*DIM];     // W lo
__device__ __half g_qa [(size_t)BB*SS*AD];     // Q   (single)
__device__ __half g_ka [(size_t)BB*SS*AD];     // K   (single)
__device__ float  g_v  [(size_t)BB*SS*AD];     // V fp32 (pre-transpose)
__device__ __half g_vta[(size_t)BB*AD*SS];     // V^T (single) [B,AD,S]
__device__ __half g_pa [(size_t)BB*SS*SS];     // unnormalized exp(s/32)

// ---------------------------------------------------------------------------
// PTX helpers (compute_103-safe: cp.async + ldmatrix + mma.sync only)
// ---------------------------------------------------------------------------
static __device__ __forceinline__ uint32_t smem_u32(const void* p) {
    uint32_t a;
    asm("{ .reg .u64 t; cvta.to.shared.u64 t, %1; cvt.u32.u64 %0, t; }" : "=r"(a) : "l"(p));
    return a;
}
#define CP_ASYNC16(dst, src) \
    asm volatile("cp.async.cg.shared.global [%0], [%1], 16;" :: "r"(dst), "l"(src))
#define CP_COMMIT() asm volatile("cp.async.commit_group;" ::: "memory")
#define CP_WAIT(n)  asm volatile("cp.async.wait_group %0;" :: "n"(n) : "memory")

static __device__ __forceinline__ void ldsm4(uint32_t& r0, uint32_t& r1, uint32_t& r2, uint32_t& r3, uint32_t addr) {
    asm volatile("ldmatrix.sync.aligned.m8n8.x4.shared.b16 {%0,%1,%2,%3}, [%4];"
                 : "=r"(r0), "=r"(r1), "=r"(r2), "=r"(r3) : "r"(addr));
}
static __device__ __forceinline__ void mma16816(float* c,
                                                uint32_t a0, uint32_t a1, uint32_t a2, uint32_t a3,
                                                uint32_t b0, uint32_t b1) {
    asm volatile("mma.sync.aligned.m16n8k16.row.col.f32.f16.f16.f32 "
                 "{%0,%1,%2,%3}, {%4,%5,%6,%7}, {%8,%9}, {%0,%1,%2,%3};"
                 : "+f"(c[0]), "+f"(c[1]), "+f"(c[2]), "+f"(c[3])
                 : "r"(a0), "r"(a1), "r"(a2), "r"(a3), "r"(b0), "r"(b1));
}

static __device__ __forceinline__ void store_split2h(__half* H, __half* L,
                                                     size_t idx, float v0, float v1) {
    __half h0 = __float2half_rn(v0), h1 = __float2half_rn(v1);
    __half l0 = __float2half_rn(v0 - __half2float(h0));
    __half l1 = __float2half_rn(v1 - __half2float(h1));
    *(__half2*)(H + idx) = __halves2half2(h0, h1);
    *(__half2*)(L + idx) = __halves2half2(l0, l1);
}
static __device__ __forceinline__ void store_h2(__half* H, size_t idx, float v0, float v1) {
    *(__half2*)(H + idx) = __halves2half2(__float2half_rn(v0), __float2half_rn(v1));
}

// ---------------------------------------------------------------------------
// HMMA core: C[128x128] += A[128xK] * B[128xK]^T.
//   SPLIT_B=true : C = A*Bh + A*Bl  (B 2-term; smem stage = A,Bh,Bl)
//   SPLIT_B=false: C = A*B          (single;   smem stage = A,B)
// 256 threads, 8 warps, warp tile 64x32. 2-stage cp.async pipeline.
// Rows padded to 80B (64B data + 16B) for conflict-free ldmatrix.
// RS: row sums of A via ones-vector MMA (PV normalization).
// ---------------------------------------------------------------------------
#define T_BYTES    10240           // 128 rows * 80B
#define SMEM_QKV   (2*3*T_BYTES)   // 61440
#define SMEM_SP    (2*2*T_BYTES)   // 40960

static __device__ __forceinline__ void stage_tile(uint32_t sdst, const __half* src,
                                                  int ld, int tid) {
    #pragma unroll
    for (int i = 0; i < 2; ++i) {
        int ci = tid * 2 + i;              // 0..511
        int r = ci >> 2, c = ci & 3;
        CP_ASYNC16(sdst + r * 80 + c * 16, (const char*)(src + (size_t)r * ld) + c * 16);
    }
}

template<bool SPLIT_B, bool RS>
static __device__ __forceinline__ void gemm128(
    const __half* __restrict__ A, int lda,
    const __half* __restrict__ Bh, const __half* __restrict__ Bl, int ldb,
    int nChunks, char* smem, float acc[16][4], float rsacc[4][4])
{
    const int STAGE_B = (SPLIT_B ? 3 : 2) * T_BYTES;
    const int tid  = threadIdx.x;
    const int lane = tid & 31;
    const int w    = tid >> 5;
    const int m_off = (w >> 2) * 64;
    const int n_off = (w & 3) * 32;
    uint32_t sb = smem_u32(smem);
    const uint32_t ONE2 = 0x3C003C00u;     // packed fp16 {1.0, 1.0}

    // ldmatrix lane-address components
    const uint32_t a_row  = (uint32_t)(lane & 15);
    const uint32_t a_koff = (uint32_t)((lane >> 4) & 1) * 16;
    const uint32_t b_row  = (uint32_t)(((lane >> 4) << 3) + (lane & 7));
    const uint32_t b_koff = (uint32_t)((lane >> 3) & 1) * 16;

    // prefetch stage 0
    {
        uint32_t st = sb;
        stage_tile(st,           A,  lda, tid);
        stage_tile(st + T_BYTES, Bh, ldb, tid);
        if (SPLIT_B) stage_tile(st + 2*T_BYTES, Bl, ldb, tid);
        CP_COMMIT();
    }

    for (int i = 0; i < nChunks; ++i) {
        if (i + 1 < nChunks) {
            uint32_t st = sb + ((i + 1) & 1) * STAGE_B;
            stage_tile(st,           A  + (size_t)(i + 1) * 32, lda, tid);
            stage_tile(st + T_BYTES, Bh + (size_t)(i + 1) * 32, ldb, tid);
            if (SPLIT_B) stage_tile(st + 2*T_BYTES, Bl + (size_t)(i + 1) * 32, ldb, tid);
            CP_COMMIT();
            CP_WAIT(1);
        } else {
            CP_WAIT(0);
        }
        __syncthreads();

        uint32_t st = sb + (i & 1) * STAGE_B;
        #pragma unroll
        for (int k16 = 0; k16 < 2; ++k16) {
            uint32_t kb = k16 * 32;       // 16 fp16 = 32 bytes
            uint32_t bh[8], bl[8];
            #pragma unroll
            for (int h = 0; h < 2; ++h) {
                uint32_t addr = st + T_BYTES + (uint32_t)(n_off + h*16 + b_row) * 80 + kb + b_koff;
                ldsm4(bh[h*4], bh[h*4+1], bh[h*4+2], bh[h*4+3], addr);
                if (SPLIT_B) ldsm4(bl[h*4], bl[h*4+1], bl[h*4+2], bl[h*4+3], addr + T_BYTES);
            }
            #pragma unroll
            for (int mf = 0; mf < 4; ++mf) {
                uint32_t addr = st + (uint32_t)(m_off + mf*16 + a_row) * 80 + kb + a_koff;
                uint32_t a0, a1, a2, a3;
                ldsm4(a0, a1, a2, a3, addr);
                if (RS) {
                    mma16816(rsacc[mf], a0, a1, a2, a3, ONE2, ONE2);   // Σ A
                }
                #pragma unroll
                for (int nf = 0; nf < 4; ++nf) {
                    float* c = acc[mf*4 + nf];
                    mma16816(c, a0, a1, a2, a3, bh[nf*2], bh[nf*2+1]);     // A*Bh
                    if (SPLIT_B)
                        mma16816(c, a0, a1, a2, a3, bl[nf*2], bl[nf*2+1]); // A*Bl
                }
            }
        }
        __syncthreads();
    }
}

// ---------------------------------------------------------------------------
// Split kernels (device globals referenced in device code only)
// ---------------------------------------------------------------------------
__global__ void __launch_bounds__(256) split_x_kernel(const float* __restrict__ s) {
    int i = (blockIdx.x * 256 + threadIdx.x) * 4;
    float4 v = *(const float4*)(s + i);
    store_h2(g_xa, i,     v.x, v.y);
    store_h2(g_xa, i + 2, v.z, v.w);
}
__global__ void __launch_bounds__(256) split_w_kernel(const float* __restrict__ s) {
    int i = (blockIdx.x * 256 + threadIdx.x) * 4;
    float4 v = *(const float4*)(s + i);
    store_split2h(g_wh, g_wl, i,     v.x, v.y);
    store_split2h(g_wh, g_wl, i + 2, v.z, v.w);
}

// ---------------------------------------------------------------------------
// QKV GEMM: [8192,3072] = x @ W^T + bias (W 2-term).
// Epilogue routes: Q, K -> single fp16; V -> fp32 (for transpose+round).
// ---------------------------------------------------------------------------
__global__ void __launch_bounds__(256, 1) qkv_mma(const float* __restrict__ bias) {
    extern __shared__ __align__(128) char sm[];
    const int m0 = blockIdx.y * 128, n0 = blockIdx.x * 128;
    const int lane = threadIdx.x & 31, w = threadIdx.x >> 5;
    const int m_off = (w >> 2) * 64, n_off = (w & 3) * 32;

    float acc[16][4];
    #pragma unroll
    for (int i = 0; i < 16; ++i)
        #pragma unroll
        for (int j = 0; j < 4; ++j) acc[i][j] = 0.0f;
    float rs_dummy[4][4];

    gemm128<true, false>(g_xa + (size_t)m0 * DIM, DIM,
                         g_wh + (size_t)n0 * DIM, g_wl + (size_t)n0 * DIM, DIM,
                         DIM / 32, sm, acc, rs_dummy);

    #pragma unroll
    for (int mf = 0; mf < 4; ++mf) {
        #pragma unroll
        for (int nf = 0; nf < 4; ++nf) {
            float* c = acc[mf*4 + nf];
            int r  = m0 + m_off + mf*16 + (lane >> 2);
            int cg = n0 + n_off + nf*8 + ((lane & 3) << 1);
            float b0 = bias[cg], b1 = bias[cg + 1];
            float v0 = c[0] + b0, v1 = c[1] + b1;     // row r
            float v2 = c[2] + b0, v3 = c[3] + b1;     // row r+8
            if (cg < AD) {
                store_h2(g_qa, (size_t)r * AD + cg,       v0, v1);
                store_h2(g_qa, (size_t)(r + 8) * AD + cg, v2, v3);
            } else if (cg < 2*AD) {
                int ck = cg - AD;
                store_h2(g_ka, (size_t)r * AD + ck,       v0, v1);
                store_h2(g_ka, (size_t)(r + 8) * AD + ck, v2, v3);
            } else {
                int cv = cg - 2*AD;
                *(float2*)(g_v + (size_t)r * AD + cv)       = make_float2(v0, v1);
                *(float2*)(g_v + (size_t)(r + 8) * AD + cv) = make_float2(v2, v3);
            }
        }
    }
}

// ---------------------------------------------------------------------------
// V transpose: g_v [B,S,AD] -> g_vta [B,AD,S] (single fp16)
// ---------------------------------------------------------------------------
__global__ void __launch_bounds__(256) vt_split_kernel() {
    __shared__ float t[32][33];
    const int b = blockIdx.z;
    const int k0 = blockIdx.x * 32, n0 = blockIdx.y * 32;
    const int tx = threadIdx.x, ty = threadIdx.y;     // 32 x 8
    const float* V = g_v + (size_t)b * SS * AD;
    #pragma unroll
    for (int j = 0; j < 4; ++j)
        t[ty + j * 8][tx] = V[(size_t)(k0 + ty + j * 8) * AD + n0 + tx];
    __syncthreads();
    #pragma unroll
    for (int j = 0; j < 4; ++j) {
        int n = n0 + ty + j * 8;
        int k = k0 + tx;
        g_vta[((size_t)b * AD + n) * SS + k] = __float2half_rn(t[tx][ty + j * 8]);
    }
}

// ---------------------------------------------------------------------------
// Scores GEMM (single fp16) + fused exp: writes UNNORMALIZED e = exp(s/32).
// Diagonal blocks mask j>i to exactly 0 (matches -inf-before-scale reference).
// ---------------------------------------------------------------------------
__global__ void __launch_bounds__(256, 1) scores_mma() {
    const int bx = blockIdx.x, by = blockIdx.y, b = blockIdx.z;
    if (bx > by) return;
    extern __shared__ __align__(128) char sm[];
    const int m0 = by * 128, n0 = bx * 128;
    const int lane = threadIdx.x & 31, w = threadIdx.x >> 5;
    const int m_off = (w >> 2) * 64, n_off = (w & 3) * 32;

    float acc[16][4];
    #pragma unroll
    for (int i = 0; i < 16; ++i)
        #pragma unroll
        for (int j = 0; j < 4; ++j) acc[i][j] = 0.0f;
    float rs_dummy[4][4];

    const size_t qo = ((size_t)b * SS + m0) * AD;
    const size_t ko = ((size_t)b * SS + n0) * AD;
    gemm128<false, false>(g_qa + qo, AD, g_ka + ko, g_ka + ko, AD,
                          AD / 32, sm, acc, rs_dummy);

    __half* pa = g_pa + (size_t)b * SS * SS;
    const float inv = 1.0f / 32.0f;
    const bool diag = (bx == by);
    #pragma unroll
    for (int mf = 0; mf < 4; ++mf) {
        #pragma unroll
        for (int nf = 0; nf < 4; ++nf) {
            float* c = acc[mf*4 + nf];
            int r  = m0 + m_off + mf*16 + (lane >> 2);
            int cg = n0 + n_off + nf*8 + ((lane & 3) << 1);
            float e0 = expf(c[0] * inv), e1 = expf(c[1] * inv);
            float e2 = expf(c[2] * inv), e3 = expf(c[3] * inv);
            if (diag) {
                if (cg     > r)     e0 = 0.0f;
                if (cg + 1 > r)     e1 = 0.0f;
                if (cg     > r + 8) e2 = 0.0f;
                if (cg + 1 > r + 8) e3 = 0.0f;
            }
            store_h2(pa, (size_t)r * SS + cg,       e0, e1);
            store_h2(pa, (size_t)(r + 8) * SS + cg, e2, e3);
        }
    }
}

// ---------------------------------------------------------------------------
// PV GEMM (single fp16): y = (E @ V) / rowsum(E), K truncated at causal edge.
// Row sums via ones-vector MMA on the SAME fp16 E used in the numerator.
// ---------------------------------------------------------------------------
__global__ void __launch_bounds__(256, 1) pv_mma(float* __restrict__ y) {
    extern __shared__ __align__(128) char sm[];
    const int b = blockIdx.z;
    const int m0 = blockIdx.y * 128, n0 = blockIdx.x * 128;
    const int lane = threadIdx.x & 31, w = threadIdx.x >> 5;
    const int m_off = (w >> 2) * 64, n_off = (w & 3) * 32;

    float acc[16][4];
    #pragma unroll
    for (int i = 0; i < 16; ++i)
        #pragma unroll
        for (int j = 0; j < 4; ++j) acc[i][j] = 0.0f;
    float rs[4][4];
    #pragma unroll
    for (int i = 0; i < 4; ++i)
        #pragma unroll
        for (int j = 0; j < 4; ++j) rs[i][j] = 0.0f;

    const size_t po = ((size_t)b * SS + m0) * SS;
    const size_t vo = ((size_t)b * AD + n0) * SS;
    gemm128<false, true>(g_pa + po, SS, g_vta + vo, g_vta + vo, SS,
                         (blockIdx.y + 1) * 4, sm, acc, rs);

    #pragma unroll
    for (int mf = 0; mf < 4; ++mf) {
        const float i0 = 1.0f / rs[mf][0];     // row r   sum
        const float i1 = 1.0f / rs[mf][2];     // row r+8 sum
        #pragma unroll
        for (int nf = 0; nf < 4; ++nf) {
            float* c = acc[mf*4 + nf];
            int r  = m0 + m_off + mf*16 + (lane >> 2);
            int cg = n0 + n_off + nf*8 + ((lane & 3) << 1);
            *(float2*)(y + ((size_t)b * SS + r) * AD + cg)     = make_float2(c[0] * i0, c[1] * i0);
            *(float2*)(y + ((size_t)b * SS + r + 8) * AD + cg) = make_float2(c[2] * i1, c[3] * i1);
        }
    }
}

// ---------------------------------------------------------------------------
extern "C" void kernel_launch(void* const* d_in, const int* in_sizes, int n_in,
                              void* d_out, int out_size)
{
    const float* x    = (const float*)d_in[0];   // [B,S,DIM]
    const float* W    = (const float*)d_in[1];   // [3*AD, DIM]
    const float* bias = (const float*)d_in[2];   // [3*AD]
    float* y = (float*)d_out;                    // [B,S,AD]

    cudaFuncSetAttribute(qkv_mma,    cudaFuncAttributeMaxDynamicSharedMemorySize, SMEM_QKV);
    cudaFuncSetAttribute(scores_mma, cudaFuncAttributeMaxDynamicSharedMemorySize, SMEM_SP);
    cudaFuncSetAttribute(pv_mma,     cudaFuncAttributeMaxDynamicSharedMemorySize, SMEM_SP);

    split_x_kernel<<<(BB*SS*DIM) / 1024, 256>>>(x);
    split_w_kernel<<<(QKV3*DIM) / 1024, 256>>>(W);
    qkv_mma   <<<dim3(QKV3/128, (BB*SS)/128), 256, SMEM_QKV>>>(bias);
    vt_split_kernel<<<dim3(SS/32, AD/32, BB), dim3(32, 8)>>>();
    scores_mma<<<dim3(SS/128, SS/128, BB), 256, SMEM_SP>>>();
    pv_mma    <<<dim3(AD/128, SS/128, BB), 256, SMEM_SP>>>(y);
}

// round 13
// speedup vs baseline: 2.3293x; 1.2130x over previous
#include <cuda_runtime.h>
#include <cuda_fp16.h>
#include <cstdint>
#include <math.h>

#define BB   2
#define SS   4096
#define DIM  1024
#define AD   1024
#define QKV3 (3*AD)

// ---------------------------------------------------------------------------
// Device scratch — all GEMM operands single fp16.
// ---------------------------------------------------------------------------
__device__ __half g_xa [(size_t)BB*SS*DIM];    // x
__device__ __half g_wa [(size_t)QKV3*DIM];     // W
__device__ __half g_qa [(size_t)BB*SS*AD];     // Q
__device__ __half g_ka [(size_t)BB*SS*AD];     // K
__device__ float  g_v  [(size_t)BB*SS*AD];     // V fp32 (pre-transpose)
__device__ __half g_vta[(size_t)BB*AD*SS];     // V^T [B,AD,S]
__device__ __half g_pa [(size_t)BB*SS*SS];     // unnormalized exp(s/32)

// ---------------------------------------------------------------------------
// PTX helpers (compute_103-safe: cp.async + ldmatrix + mma.sync only)
// ---------------------------------------------------------------------------
static __device__ __forceinline__ uint32_t smem_u32(const void* p) {
    uint32_t a;
    asm("{ .reg .u64 t; cvta.to.shared.u64 t, %1; cvt.u32.u64 %0, t; }" : "=r"(a) : "l"(p));
    return a;
}
#define CP_ASYNC16(dst, src) \
    asm volatile("cp.async.cg.shared.global [%0], [%1], 16;" :: "r"(dst), "l"(src))
#define CP_COMMIT() asm volatile("cp.async.commit_group;" ::: "memory")
#define CP_WAIT(n)  asm volatile("cp.async.wait_group %0;" :: "n"(n) : "memory")

static __device__ __forceinline__ void ldsm4(uint32_t& r0, uint32_t& r1, uint32_t& r2, uint32_t& r3, uint32_t addr) {
    asm volatile("ldmatrix.sync.aligned.m8n8.x4.shared.b16 {%0,%1,%2,%3}, [%4];"
                 : "=r"(r0), "=r"(r1), "=r"(r2), "=r"(r3) : "r"(addr));
}
static __device__ __forceinline__ void mma16816(float* c,
                                                uint32_t a0, uint32_t a1, uint32_t a2, uint32_t a3,
                                                uint32_t b0, uint32_t b1) {
    asm volatile("mma.sync.aligned.m16n8k16.row.col.f32.f16.f16.f32 "
                 "{%0,%1,%2,%3}, {%4,%5,%6,%7}, {%8,%9}, {%0,%1,%2,%3};"
                 : "+f"(c[0]), "+f"(c[1]), "+f"(c[2]), "+f"(c[3])
                 : "r"(a0), "r"(a1), "r"(a2), "r"(a3), "r"(b0), "r"(b1));
}

static __device__ __forceinline__ void store_h2(__half* H, size_t idx, float v0, float v1) {
    *(__half2*)(H + idx) = __halves2half2(__float2half_rn(v0), __float2half_rn(v1));
}

// ---------------------------------------------------------------------------
// HMMA core: C[128x128] += A[128xK] * B[128xK]^T, single fp16.
// 256 threads, 8 warps, warp tile 64x32. 2-stage cp.async pipeline.
// Rows padded to 80B (64B data + 16B) for conflict-free ldmatrix.
// RS: row sums of A via ones-vector MMA (PV normalization).
// ---------------------------------------------------------------------------
#define T_BYTES    10240           // 128 rows * 80B
#define STAGE_B    (2*T_BYTES)     // 20480
#define SMEM_TOTAL (2*STAGE_B)     // 40960

static __device__ __forceinline__ void stage_tile(uint32_t sdst, const __half* src,
                                                  int ld, int tid) {
    #pragma unroll
    for (int i = 0; i < 2; ++i) {
        int ci = tid * 2 + i;              // 0..511
        int r = ci >> 2, c = ci & 3;
        CP_ASYNC16(sdst + r * 80 + c * 16, (const char*)(src + (size_t)r * ld) + c * 16);
    }
}

template<bool RS>
static __device__ __forceinline__ void gemm128(
    const __half* __restrict__ A, int lda,
    const __half* __restrict__ B, int ldb,
    int nChunks, char* smem, float acc[16][4], float rsacc[4][4])
{
    const int tid  = threadIdx.x;
    const int lane = tid & 31;
    const int w    = tid >> 5;
    const int m_off = (w >> 2) * 64;
    const int n_off = (w & 3) * 32;
    uint32_t sb = smem_u32(smem);
    const uint32_t ONE2 = 0x3C003C00u;     // packed fp16 {1.0, 1.0}

    // ldmatrix lane-address components
    const uint32_t a_row  = (uint32_t)(lane & 15);
    const uint32_t a_koff = (uint32_t)((lane >> 4) & 1) * 16;
    const uint32_t b_row  = (uint32_t)(((lane >> 4) << 3) + (lane & 7));
    const uint32_t b_koff = (uint32_t)((lane >> 3) & 1) * 16;

    // prefetch stage 0
    {
        uint32_t st = sb;
        stage_tile(st,           A, lda, tid);
        stage_tile(st + T_BYTES, B, ldb, tid);
        CP_COMMIT();
    }

    for (int i = 0; i < nChunks; ++i) {
        if (i + 1 < nChunks) {
            uint32_t st = sb + ((i + 1) & 1) * STAGE_B;
            stage_tile(st,           A + (size_t)(i + 1) * 32, lda, tid);
            stage_tile(st + T_BYTES, B + (size_t)(i + 1) * 32, ldb, tid);
            CP_COMMIT();
            CP_WAIT(1);
        } else {
            CP_WAIT(0);
        }
        __syncthreads();

        uint32_t st = sb + (i & 1) * STAGE_B;
        #pragma unroll
        for (int k16 = 0; k16 < 2; ++k16) {
            uint32_t kb = k16 * 32;       // 16 fp16 = 32 bytes
            uint32_t bh[8];
            #pragma unroll
            for (int h = 0; h < 2; ++h) {
                uint32_t addr = st + T_BYTES + (uint32_t)(n_off + h*16 + b_row) * 80 + kb + b_koff;
                ldsm4(bh[h*4], bh[h*4+1], bh[h*4+2], bh[h*4+3], addr);
            }
            #pragma unroll
            for (int mf = 0; mf < 4; ++mf) {
                uint32_t addr = st + (uint32_t)(m_off + mf*16 + a_row) * 80 + kb + a_koff;
                uint32_t a0, a1, a2, a3;
                ldsm4(a0, a1, a2, a3, addr);
                if (RS) {
                    mma16816(rsacc[mf], a0, a1, a2, a3, ONE2, ONE2);   // Σ A
                }
                #pragma unroll
                for (int nf = 0; nf < 4; ++nf) {
                    mma16816(acc[mf*4 + nf], a0, a1, a2, a3, bh[nf*2], bh[nf*2+1]);
                }
            }
        }
        __syncthreads();
    }
}

// ---------------------------------------------------------------------------
// Convert kernels: fp32 -> single fp16 (device globals in device code only)
// ---------------------------------------------------------------------------
__global__ void __launch_bounds__(256) split_x_kernel(const float* __restrict__ s) {
    int i = (blockIdx.x * 256 + threadIdx.x) * 4;
    float4 v = *(const float4*)(s + i);
    store_h2(g_xa, i,     v.x, v.y);
    store_h2(g_xa, i + 2, v.z, v.w);
}
__global__ void __launch_bounds__(256) split_w_kernel(const float* __restrict__ s) {
    int i = (blockIdx.x * 256 + threadIdx.x) * 4;
    float4 v = *(const float4*)(s + i);
    store_h2(g_wa, i,     v.x, v.y);
    store_h2(g_wa, i + 2, v.z, v.w);
}

// ---------------------------------------------------------------------------
// QKV GEMM: [8192,3072] = x @ W^T + bias.
// Epilogue routes: Q, K -> single fp16; V -> fp32 (for transpose+round).
// ---------------------------------------------------------------------------
__global__ void __launch_bounds__(256, 1) qkv_mma(const float* __restrict__ bias) {
    extern __shared__ __align__(128) char sm[];
    const int m0 = blockIdx.y * 128, n0 = blockIdx.x * 128;
    const int lane = threadIdx.x & 31, w = threadIdx.x >> 5;
    const int m_off = (w >> 2) * 64, n_off = (w & 3) * 32;

    float acc[16][4];
    #pragma unroll
    for (int i = 0; i < 16; ++i)
        #pragma unroll
        for (int j = 0; j < 4; ++j) acc[i][j] = 0.0f;
    float rs_dummy[4][4];

    gemm128<false>(g_xa + (size_t)m0 * DIM, DIM,
                   g_wa + (size_t)n0 * DIM, DIM,
                   DIM / 32, sm, acc, rs_dummy);

    #pragma unroll
    for (int mf = 0; mf < 4; ++mf) {
        #pragma unroll
        for (int nf = 0; nf < 4; ++nf) {
            float* c = acc[mf*4 + nf];
            int r  = m0 + m_off + mf*16 + (lane >> 2);
            int cg = n0 + n_off + nf*8 + ((lane & 3) << 1);
            float b0 = bias[cg], b1 = bias[cg + 1];
            float v0 = c[0] + b0, v1 = c[1] + b1;     // row r
            float v2 = c[2] + b0, v3 = c[3] + b1;     // row r+8
            if (cg < AD) {
                store_h2(g_qa, (size_t)r * AD + cg,       v0, v1);
                store_h2(g_qa, (size_t)(r + 8) * AD + cg, v2, v3);
            } else if (cg < 2*AD) {
                int ck = cg - AD;
                store_h2(g_ka, (size_t)r * AD + ck,       v0, v1);
                store_h2(g_ka, (size_t)(r + 8) * AD + ck, v2, v3);
            } else {
                int cv = cg - 2*AD;
                *(float2*)(g_v + (size_t)r * AD + cv)       = make_float2(v0, v1);
                *(float2*)(g_v + (size_t)(r + 8) * AD + cv) = make_float2(v2, v3);
            }
        }
    }
}

// ---------------------------------------------------------------------------
// V transpose: g_v [B,S,AD] -> g_vta [B,AD,S] (single fp16)
// ---------------------------------------------------------------------------
__global__ void __launch_bounds__(256) vt_split_kernel() {
    __shared__ float t[32][33];
    const int b = blockIdx.z;
    const int k0 = blockIdx.x * 32, n0 = blockIdx.y * 32;
    const int tx = threadIdx.x, ty = threadIdx.y;     // 32 x 8
    const float* V = g_v + (size_t)b * SS * AD;
    #pragma unroll
    for (int j = 0; j < 4; ++j)
        t[ty + j * 8][tx] = V[(size_t)(k0 + ty + j * 8) * AD + n0 + tx];
    __syncthreads();
    #pragma unroll
    for (int j = 0; j < 4; ++j) {
        int n = n0 + ty + j * 8;
        int k = k0 + tx;
        g_vta[((size_t)b * AD + n) * SS + k] = __float2half_rn(t[tx][ty + j * 8]);
    }
}

// ---------------------------------------------------------------------------
// Scores GEMM + fused exp: writes UNNORMALIZED e = exp(s/32) as fp16.
// Diagonal blocks mask j>i to exactly 0 (matches -inf-before-scale reference).
// ---------------------------------------------------------------------------
__global__ void __launch_bounds__(256, 1) scores_mma() {
    const int bx = blockIdx.x, by = blockIdx.y, b = blockIdx.z;
    if (bx > by) return;
    extern __shared__ __align__(128) char sm[];
    const int m0 = by * 128, n0 = bx * 128;
    const int lane = threadIdx.x & 31, w = threadIdx.x >> 5;
    const int m_off = (w >> 2) * 64, n_off = (w & 3) * 32;

    float acc[16][4];
    #pragma unroll
    for (int i = 0; i < 16; ++i)
        #pragma unroll
        for (int j = 0; j < 4; ++j) acc[i][j] = 0.0f;
    float rs_dummy[4][4];

    const size_t qo = ((size_t)b * SS + m0) * AD;
    const size_t ko = ((size_t)b * SS + n0) * AD;
    gemm128<false>(g_qa + qo, AD, g_ka + ko, AD, AD / 32, sm, acc, rs_dummy);

    __half* pa = g_pa + (size_t)b * SS * SS;
    const float inv = 1.0f / 32.0f;
    const bool diag = (bx == by);
    #pragma unroll
    for (int mf = 0; mf < 4; ++mf) {
        #pragma unroll
        for (int nf = 0; nf < 4; ++nf) {
            float* c = acc[mf*4 + nf];
            int r  = m0 + m_off + mf*16 + (lane >> 2);
            int cg = n0 + n_off + nf*8 + ((lane & 3) << 1);
            float e0 = expf(c[0] * inv), e1 = expf(c[1] * inv);
            float e2 = expf(c[2] * inv), e3 = expf(c[3] * inv);
            if (diag) {
                if (cg     > r)     e0 = 0.0f;
                if (cg + 1 > r)     e1 = 0.0f;
                if (cg     > r + 8) e2 = 0.0f;
                if (cg + 1 > r + 8) e3 = 0.0f;
            }
            store_h2(pa, (size_t)r * SS + cg,       e0, e1);
            store_h2(pa, (size_t)(r + 8) * SS + cg, e2, e3);
        }
    }
}

// ---------------------------------------------------------------------------
// PV GEMM: y = (E @ V) / rowsum(E), K truncated at causal boundary.
// Row sums via ones-vector MMA on the SAME fp16 E used in the numerator.
// ---------------------------------------------------------------------------
__global__ void __launch_bounds__(256, 1) pv_mma(float* __restrict__ y) {
    extern __shared__ __align__(128) char sm[];
    const int b = blockIdx.z;
    const int m0 = blockIdx.y * 128, n0 = blockIdx.x * 128;
    const int lane = threadIdx.x & 31, w = threadIdx.x >> 5;
    const int m_off = (w >> 2) * 64, n_off = (w & 3) * 32;

    float acc[16][4];
    #pragma unroll
    for (int i = 0; i < 16; ++i)
        #pragma unroll
        for (int j = 0; j < 4; ++j) acc[i][j] = 0.0f;
    float rs[4][4];
    #pragma unroll
    for (int i = 0; i < 4; ++i)
        #pragma unroll
        for (int j = 0; j < 4; ++j) rs[i][j] = 0.0f;

    const size_t po = ((size_t)b * SS + m0) * SS;
    const size_t vo = ((size_t)b * AD + n0) * SS;
    gemm128<true>(g_pa + po, SS, g_vta + vo, SS,
                  (blockIdx.y + 1) * 4, sm, acc, rs);

    #pragma unroll
    for (int mf = 0; mf < 4; ++mf) {
        const float i0 = 1.0f / rs[mf][0];     // row r   sum
        const float i1 = 1.0f / rs[mf][2];     // row r+8 sum
        #pragma unroll
        for (int nf = 0; nf < 4; ++nf) {
            float* c = acc[mf*4 + nf];
            int r  = m0 + m_off + mf*16 + (lane >> 2);
            int cg = n0 + n_off + nf*8 + ((lane & 3) << 1);
            *(float2*)(y + ((size_t)b * SS + r) * AD + cg)     = make_float2(c[0] * i0, c[1] * i0);
            *(float2*)(y + ((size_t)b * SS + r + 8) * AD + cg) = make_float2(c[2] * i1, c[3] * i1);
        }
    }
}

// ---------------------------------------------------------------------------
extern "C" void kernel_launch(void* const* d_in, const int* in_sizes, int n_in,
                              void* d_out, int out_size)
{
    const float* x    = (const float*)d_in[0];   // [B,S,DIM]
    const float* W    = (const float*)d_in[1];   // [3*AD, DIM]
    const float* bias = (const float*)d_in[2];   // [3*AD]
    float* y = (float*)d_out;                    // [B,S,AD]

    cudaFuncSetAttribute(qkv_mma,    cudaFuncAttributeMaxDynamicSharedMemorySize, SMEM_TOTAL);
    cudaFuncSetAttribute(scores_mma, cudaFuncAttributeMaxDynamicSharedMemorySize, SMEM_TOTAL);
    cudaFuncSetAttribute(pv_mma,     cudaFuncAttributeMaxDynamicSharedMemorySize, SMEM_TOTAL);

    split_x_kernel<<<(BB*SS*DIM) / 1024, 256>>>(x);
    split_w_kernel<<<(QKV3*DIM) / 1024, 256>>>(W);
    qkv_mma   <<<dim3(QKV3/128, (BB*SS)/128), 256, SMEM_TOTAL>>>(bias);
    vt_split_kernel<<<dim3(SS/32, AD/32, BB), dim3(32, 8)>>>();
    scores_mma<<<dim3(SS/128, SS/128, BB), 256, SMEM_TOTAL>>>();
    pv_mma    <<<dim3(AD/128, SS/128, BB), 256, SMEM_TOTAL>>>(y);
}

// round 15
// speedup vs baseline: 3.0618x; 1.3145x over previous
#include <cuda_runtime.h>
#include <cuda_fp16.h>
#include <cstdint>
#include <math.h>

#define BB   2
#define SS   4096
#define DIM  1024
#define AD   1024
#define QKV3 (3*AD)

// ---------------------------------------------------------------------------
// Device scratch — all GEMM operands single fp16.
// ---------------------------------------------------------------------------
__device__ __half g_xa [(size_t)BB*SS*DIM];    // x
__device__ __half g_wa [(size_t)QKV3*DIM];     // W
__device__ __half g_qa [(size_t)BB*SS*AD];     // Q
__device__ __half g_ka [(size_t)BB*SS*AD];     // K
__device__ float  g_v  [(size_t)BB*SS*AD];     // V fp32 (pre-transpose)
__device__ __half g_vta[(size_t)BB*AD*SS];     // V^T [B,AD,S]
__device__ __half g_pa [(size_t)BB*SS*SS];     // unnormalized exp(s/32)

// ---------------------------------------------------------------------------
// PTX helpers (compute_103-safe: cp.async + ldmatrix + mma.sync only)
// ---------------------------------------------------------------------------
static __device__ __forceinline__ uint32_t smem_u32(const void* p) {
    uint32_t a;
    asm("{ .reg .u64 t; cvta.to.shared.u64 t, %1; cvt.u32.u64 %0, t; }" : "=r"(a) : "l"(p));
    return a;
}
#define CP_ASYNC16(dst, src) \
    asm volatile("cp.async.cg.shared.global [%0], [%1], 16;" :: "r"(dst), "l"(src))
#define CP_COMMIT() asm volatile("cp.async.commit_group;" ::: "memory")
#define CP_WAIT(n)  asm volatile("cp.async.wait_group %0;" :: "n"(n) : "memory")

static __device__ __forceinline__ void ldsm4(uint32_t& r0, uint32_t& r1, uint32_t& r2, uint32_t& r3, uint32_t addr) {
    asm volatile("ldmatrix.sync.aligned.m8n8.x4.shared.b16 {%0,%1,%2,%3}, [%4];"
                 : "=r"(r0), "=r"(r1), "=r"(r2), "=r"(r3) : "r"(addr));
}
static __device__ __forceinline__ void mma16816(float* c,
                                                uint32_t a0, uint32_t a1, uint32_t a2, uint32_t a3,
                                                uint32_t b0, uint32_t b1) {
    asm volatile("mma.sync.aligned.m16n8k16.row.col.f32.f16.f16.f32 "
                 "{%0,%1,%2,%3}, {%4,%5,%6,%7}, {%8,%9}, {%0,%1,%2,%3};"
                 : "+f"(c[0]), "+f"(c[1]), "+f"(c[2]), "+f"(c[3])
                 : "r"(a0), "r"(a1), "r"(a2), "r"(a3), "r"(b0), "r"(b1));
}

static __device__ __forceinline__ void store_h2(__half* H, size_t idx, float v0, float v1) {
    *(__half2*)(H + idx) = __halves2half2(__float2half_rn(v0), __float2half_rn(v1));
}

// ---------------------------------------------------------------------------
// HMMA core: C[128x128] += A[128xK] * B[128xK]^T, single fp16.
// 256 threads, 8 warps, warp tile 64x32. 2-stage cp.async pipeline.
// Rows padded to 80B (64B data + 16B) for conflict-free ldmatrix.
// 40KB smem/CTA + <=128 regs -> 2 CTAs/SM; co-resident CTA hides sync bubbles.
// RS: row sums of A via ones-vector MMA (PV normalization).
// ---------------------------------------------------------------------------
#define T_BYTES    10240           // 128 rows * 80B
#define STAGE_B    (2*T_BYTES)     // 20480
#define SMEM_TOTAL (2*STAGE_B)     // 40960

static __device__ __forceinline__ void stage_tile(uint32_t sdst, const __half* src,
                                                  int ld, int tid) {
    #pragma unroll
    for (int i = 0; i < 2; ++i) {
        int ci = tid * 2 + i;              // 0..511
        int r = ci >> 2, c = ci & 3;
        CP_ASYNC16(sdst + r * 80 + c * 16, (const char*)(src + (size_t)r * ld) + c * 16);
    }
}

template<bool RS>
static __device__ __forceinline__ void gemm128(
    const __half* __restrict__ A, int lda,
    const __half* __restrict__ B, int ldb,
    int nChunks, char* smem, float acc[16][4], float rsacc[4][4])
{
    const int tid  = threadIdx.x;
    const int lane = tid & 31;
    const int w    = tid >> 5;
    const int m_off = (w >> 2) * 64;
    const int n_off = (w & 3) * 32;
    uint32_t sb = smem_u32(smem);
    const uint32_t ONE2 = 0x3C003C00u;     // packed fp16 {1.0, 1.0}

    // ldmatrix lane-address components
    const uint32_t a_row  = (uint32_t)(lane & 15);
    const uint32_t a_koff = (uint32_t)((lane >> 4) & 1) * 16;
    const uint32_t b_row  = (uint32_t)(((lane >> 4) << 3) + (lane & 7));
    const uint32_t b_koff = (uint32_t)((lane >> 3) & 1) * 16;

    // prefetch stage 0
    {
        uint32_t st = sb;
        stage_tile(st,           A, lda, tid);
        stage_tile(st + T_BYTES, B, ldb, tid);
        CP_COMMIT();
    }

    for (int i = 0; i < nChunks; ++i) {
        if (i + 1 < nChunks) {
            uint32_t st = sb + ((i + 1) & 1) * STAGE_B;
            stage_tile(st,           A + (size_t)(i + 1) * 32, lda, tid);
            stage_tile(st + T_BYTES, B + (size_t)(i + 1) * 32, ldb, tid);
            CP_COMMIT();
            CP_WAIT(1);
        } else {
            CP_WAIT(0);
        }
        __syncthreads();

        uint32_t st = sb + (i & 1) * STAGE_B;
        #pragma unroll
        for (int k16 = 0; k16 < 2; ++k16) {
            uint32_t kb = k16 * 32;       // 16 fp16 = 32 bytes
            uint32_t bh[8];
            #pragma unroll
            for (int h = 0; h < 2; ++h) {
                uint32_t addr = st + T_BYTES + (uint32_t)(n_off + h*16 + b_row) * 80 + kb + b_koff;
                ldsm4(bh[h*4], bh[h*4+1], bh[h*4+2], bh[h*4+3], addr);
            }
            #pragma unroll
            for (int mf = 0; mf < 4; ++mf) {
                uint32_t addr = st + (uint32_t)(m_off + mf*16 + a_row) * 80 + kb + a_koff;
                uint32_t a0, a1, a2, a3;
                ldsm4(a0, a1, a2, a3, addr);
                if (RS) {
                    mma16816(rsacc[mf], a0, a1, a2, a3, ONE2, ONE2);   // Σ A
                }
                #pragma unroll
                for (int nf = 0; nf < 4; ++nf) {
                    mma16816(acc[mf*4 + nf], a0, a1, a2, a3, bh[nf*2], bh[nf*2+1]);
                }
            }
        }
        __syncthreads();
    }
}

// ---------------------------------------------------------------------------
// Convert kernels: fp32 -> single fp16 (device globals in device code only)
// ---------------------------------------------------------------------------
__global__ void __launch_bounds__(256) split_x_kernel(const float* __restrict__ s) {
    int i = (blockIdx.x * 256 + threadIdx.x) * 4;
    float4 v = *(const float4*)(s + i);
    store_h2(g_xa, i,     v.x, v.y);
    store_h2(g_xa, i + 2, v.z, v.w);
}
__global__ void __launch_bounds__(256) split_w_kernel(const float* __restrict__ s) {
    int i = (blockIdx.x * 256 + threadIdx.x) * 4;
    float4 v = *(const float4*)(s + i);
    store_h2(g_wa, i,     v.x, v.y);
    store_h2(g_wa, i + 2, v.z, v.w);
}

// ---------------------------------------------------------------------------
// QKV GEMM: [8192,3072] = x @ W^T + bias.
// Epilogue routes: Q, K -> single fp16; V -> fp32 (for transpose+round).
// ---------------------------------------------------------------------------
__global__ void __launch_bounds__(256, 2) qkv_mma(const float* __restrict__ bias) {
    extern __shared__ __align__(128) char sm[];
    const int m0 = blockIdx.y * 128, n0 = blockIdx.x * 128;
    const int lane = threadIdx.x & 31, w = threadIdx.x >> 5;
    const int m_off = (w >> 2) * 64, n_off = (w & 3) * 32;

    float acc[16][4];
    #pragma unroll
    for (int i = 0; i < 16; ++i)
        #pragma unroll
        for (int j = 0; j < 4; ++j) acc[i][j] = 0.0f;
    float rs_dummy[4][4];

    gemm128<false>(g_xa + (size_t)m0 * DIM, DIM,
                   g_wa + (size_t)n0 * DIM, DIM,
                   DIM / 32, sm, acc, rs_dummy);

    #pragma unroll
    for (int mf = 0; mf < 4; ++mf) {
        #pragma unroll
        for (int nf = 0; nf < 4; ++nf) {
            float* c = acc[mf*4 + nf];
            int r  = m0 + m_off + mf*16 + (lane >> 2);
            int cg = n0 + n_off + nf*8 + ((lane & 3) << 1);
            float b0 = bias[cg], b1 = bias[cg + 1];
            float v0 = c[0] + b0, v1 = c[1] + b1;     // row r
            float v2 = c[2] + b0, v3 = c[3] + b1;     // row r+8
            if (cg < AD) {
                store_h2(g_qa, (size_t)r * AD + cg,       v0, v1);
                store_h2(g_qa, (size_t)(r + 8) * AD + cg, v2, v3);
            } else if (cg < 2*AD) {
                int ck = cg - AD;
                store_h2(g_ka, (size_t)r * AD + ck,       v0, v1);
                store_h2(g_ka, (size_t)(r + 8) * AD + ck, v2, v3);
            } else {
                int cv = cg - 2*AD;
                *(float2*)(g_v + (size_t)r * AD + cv)       = make_float2(v0, v1);
                *(float2*)(g_v + (size_t)(r + 8) * AD + cv) = make_float2(v2, v3);
            }
        }
    }
}

// ---------------------------------------------------------------------------
// V transpose: g_v [B,S,AD] -> g_vta [B,AD,S] (single fp16)
// ---------------------------------------------------------------------------
__global__ void __launch_bounds__(256) vt_split_kernel() {
    __shared__ float t[32][33];
    const int b = blockIdx.z;
    const int k0 = blockIdx.x * 32, n0 = blockIdx.y * 32;
    const int tx = threadIdx.x, ty = threadIdx.y;     // 32 x 8
    const float* V = g_v + (size_t)b * SS * AD;
    #pragma unroll
    for (int j = 0; j < 4; ++j)
        t[ty + j * 8][tx] = V[(size_t)(k0 + ty + j * 8) * AD + n0 + tx];
    __syncthreads();
    #pragma unroll
    for (int j = 0; j < 4; ++j) {
        int n = n0 + ty + j * 8;
        int k = k0 + tx;
        g_vta[((size_t)b * AD + n) * SS + k] = __float2half_rn(t[tx][ty + j * 8]);
    }
}

// ---------------------------------------------------------------------------
// Scores GEMM + fused exp: writes UNNORMALIZED e = exp(s/32) as fp16.
// Diagonal blocks mask j>i to exactly 0 (matches -inf-before-scale reference).
// ---------------------------------------------------------------------------
__global__ void __launch_bounds__(256, 2) scores_mma() {
    const int bx = blockIdx.x, by = blockIdx.y, b = blockIdx.z;
    if (bx > by) return;
    extern __shared__ __align__(128) char sm[];
    const int m0 = by * 128, n0 = bx * 128;
    const int lane = threadIdx.x & 31, w = threadIdx.x >> 5;
    const int m_off = (w >> 2) * 64, n_off = (w & 3) * 32;

    float acc[16][4];
    #pragma unroll
    for (int i = 0; i < 16; ++i)
        #pragma unroll
        for (int j = 0; j < 4; ++j) acc[i][j] = 0.0f;
    float rs_dummy[4][4];

    const size_t qo = ((size_t)b * SS + m0) * AD;
    const size_t ko = ((size_t)b * SS + n0) * AD;
    gemm128<false>(g_qa + qo, AD, g_ka + ko, AD, AD / 32, sm, acc, rs_dummy);

    __half* pa = g_pa + (size_t)b * SS * SS;
    const float inv = 1.0f / 32.0f;
    const bool diag = (bx == by);
    #pragma unroll
    for (int mf = 0; mf < 4; ++mf) {
        #pragma unroll
        for (int nf = 0; nf < 4; ++nf) {
            float* c = acc[mf*4 + nf];
            int r  = m0 + m_off + mf*16 + (lane >> 2);
            int cg = n0 + n_off + nf*8 + ((lane & 3) << 1);
            float e0 = expf(c[0] * inv), e1 = expf(c[1] * inv);
            float e2 = expf(c[2] * inv), e3 = expf(c[3] * inv);
            if (diag) {
                if (cg     > r)     e0 = 0.0f;
                if (cg + 1 > r)     e1 = 0.0f;
                if (cg     > r + 8) e2 = 0.0f;
                if (cg + 1 > r + 8) e3 = 0.0f;
            }
            store_h2(pa, (size_t)r * SS + cg,       e0, e1);
            store_h2(pa, (size_t)(r + 8) * SS + cg, e2, e3);
        }
    }
}

// ---------------------------------------------------------------------------
// PV GEMM: y = (E @ V) / rowsum(E), K truncated at causal boundary.
// Heavy-first scheduling: by remapped so 128-chunk CTAs launch in wave 1.
// Row sums via ones-vector MMA on the SAME fp16 E used in the numerator.
// ---------------------------------------------------------------------------
__global__ void __launch_bounds__(256, 2) pv_mma(float* __restrict__ y) {
    extern __shared__ __align__(128) char sm[];
    const int b = blockIdx.z;
    const int byr = (int)gridDim.y - 1 - (int)blockIdx.y;   // heavy tiles first
    const int m0 = byr * 128, n0 = blockIdx.x * 128;
    const int lane = threadIdx.x & 31, w = threadIdx.x >> 5;
    const int m_off = (w >> 2) * 64, n_off = (w & 3) * 32;

    float acc[16][4];
    #pragma unroll
    for (int i = 0; i < 16; ++i)
        #pragma unroll
        for (int j = 0; j < 4; ++j) acc[i][j] = 0.0f;
    float rs[4][4];
    #pragma unroll
    for (int i = 0; i < 4; ++i)
        #pragma unroll
        for (int j = 0; j < 4; ++j) rs[i][j] = 0.0f;

    const size_t po = ((size_t)b * SS + m0) * SS;
    const size_t vo = ((size_t)b * AD + n0) * SS;
    gemm128<true>(g_pa + po, SS, g_vta + vo, SS,
                  (byr + 1) * 4, sm, acc, rs);

    #pragma unroll
    for (int mf = 0; mf < 4; ++mf) {
        const float i0 = 1.0f / rs[mf][0];     // row r   sum
        const float i1 = 1.0f / rs[mf][2];     // row r+8 sum
        #pragma unroll
        for (int nf = 0; nf < 4; ++nf) {
            float* c = acc[mf*4 + nf];
            int r  = m0 + m_off + mf*16 + (lane >> 2);
            int cg = n0 + n_off + nf*8 + ((lane & 3) << 1);
            *(float2*)(y + ((size_t)b * SS + r) * AD + cg)     = make_float2(c[0] * i0, c[1] * i0);
            *(float2*)(y + ((size_t)b * SS + r + 8) * AD + cg) = make_float2(c[2] * i1, c[3] * i1);
        }
    }
}

// ---------------------------------------------------------------------------
extern "C" void kernel_launch(void* const* d_in, const int* in_sizes, int n_in,
                              void* d_out, int out_size)
{
    const float* x    = (const float*)d_in[0];   // [B,S,DIM]
    const float* W    = (const float*)d_in[1];   // [3*AD, DIM]
    const float* bias = (const float*)d_in[2];   // [3*AD]
    float* y = (float*)d_out;                    // [B,S,AD]

    cudaFuncSetAttribute(qkv_mma,    cudaFuncAttributeMaxDynamicSharedMemorySize, SMEM_TOTAL);
    cudaFuncSetAttribute(scores_mma, cudaFuncAttributeMaxDynamicSharedMemorySize, SMEM_TOTAL);
    cudaFuncSetAttribute(pv_mma,     cudaFuncAttributeMaxDynamicSharedMemorySize, SMEM_TOTAL);

    split_x_kernel<<<(BB*SS*DIM) / 1024, 256>>>(x);
    split_w_kernel<<<(QKV3*DIM) / 1024, 256>>>(W);
    qkv_mma   <<<dim3(QKV3/128, (BB*SS)/128), 256, SMEM_TOTAL>>>(bias);
    vt_split_kernel<<<dim3(SS/32, AD/32, BB), dim3(32, 8)>>>();
    scores_mma<<<dim3(SS/128, SS/128, BB), 256, SMEM_TOTAL>>>();
    pv_mma    <<<dim3(AD/128, SS/128, BB), 256, SMEM_TOTAL>>>(y);
}

// round 17
// speedup vs baseline: 3.0622x; 1.0001x over previous
#include <cuda_runtime.h>
#include <cuda_fp16.h>
#include <cstdint>
#include <math.h>

#define BB   2
#define SS   4096
#define DIM  1024
#define AD   1024
#define QKV3 (3*AD)

// ---------------------------------------------------------------------------
// Device scratch — all GEMM operands single fp16.
// ---------------------------------------------------------------------------
__device__ __half g_xa [(size_t)BB*SS*DIM];    // x
__device__ __half g_wa [(size_t)QKV3*DIM];     // W
__device__ __half g_qa [(size_t)BB*SS*AD];     // Q
__device__ __half g_ka [(size_t)BB*SS*AD];     // K
__device__ __half g_va [(size_t)BB*SS*AD];     // V fp16 row-major (pre-transpose)
__device__ __half g_vta[(size_t)BB*AD*SS];     // V^T [B,AD,S]
__device__ __half g_pa [(size_t)BB*SS*SS];     // unnormalized exp(s/32)

// ---------------------------------------------------------------------------
// PTX helpers (compute_103-safe: cp.async + ldmatrix + mma.sync only)
// ---------------------------------------------------------------------------
static __device__ __forceinline__ uint32_t smem_u32(const void* p) {
    uint32_t a;
    asm("{ .reg .u64 t; cvta.to.shared.u64 t, %1; cvt.u32.u64 %0, t; }" : "=r"(a) : "l"(p));
    return a;
}
#define CP_ASYNC16(dst, src) \
    asm volatile("cp.async.cg.shared.global [%0], [%1], 16;" :: "r"(dst), "l"(src))
#define CP_COMMIT() asm volatile("cp.async.commit_group;" ::: "memory")
#define CP_WAIT(n)  asm volatile("cp.async.wait_group %0;" :: "n"(n) : "memory")

static __device__ __forceinline__ void ldsm4(uint32_t& r0, uint32_t& r1, uint32_t& r2, uint32_t& r3, uint32_t addr) {
    asm volatile("ldmatrix.sync.aligned.m8n8.x4.shared.b16 {%0,%1,%2,%3}, [%4];"
                 : "=r"(r0), "=r"(r1), "=r"(r2), "=r"(r3) : "r"(addr));
}
static __device__ __forceinline__ void mma16816(float* c,
                                                uint32_t a0, uint32_t a1, uint32_t a2, uint32_t a3,
                                                uint32_t b0, uint32_t b1) {
    asm volatile("mma.sync.aligned.m16n8k16.row.col.f32.f16.f16.f32 "
                 "{%0,%1,%2,%3}, {%4,%5,%6,%7}, {%8,%9}, {%0,%1,%2,%3};"
                 : "+f"(c[0]), "+f"(c[1]), "+f"(c[2]), "+f"(c[3])
                 : "r"(a0), "r"(a1), "r"(a2), "r"(a3), "r"(b0), "r"(b1));
}

static __device__ __forceinline__ void store_h2(__half* H, size_t idx, float v0, float v1) {
    *(__half2*)(H + idx) = __halves2half2(__float2half_rn(v0), __float2half_rn(v1));
}

// ---------------------------------------------------------------------------
// HMMA core: C[128x128] += A[128xK] * B[128xK]^T, single fp16.
// 256 threads, 8 warps, warp tile 64x32. 2-stage cp.async pipeline.
// Rows padded to 80B (64B data + 16B) for conflict-free ldmatrix.
// 40KB smem/CTA + <=128 regs -> 2 CTAs/SM; co-resident CTA hides sync bubbles.
// RS: row sums of A via ones-vector MMA (PV normalization).
// ---------------------------------------------------------------------------
#define T_BYTES    10240           // 128 rows * 80B
#define STAGE_B    (2*T_BYTES)     // 20480
#define SMEM_TOTAL (2*STAGE_B)     // 40960

static __device__ __forceinline__ void stage_tile(uint32_t sdst, const __half* src,
                                                  int ld, int tid) {
    #pragma unroll
    for (int i = 0; i < 2; ++i) {
        int ci = tid * 2 + i;              // 0..511
        int r = ci >> 2, c = ci & 3;
        CP_ASYNC16(sdst + r * 80 + c * 16, (const char*)(src + (size_t)r * ld) + c * 16);
    }
}

template<bool RS>
static __device__ __forceinline__ void gemm128(
    const __half* __restrict__ A, int lda,
    const __half* __restrict__ B, int ldb,
    int nChunks, char* smem, float acc[16][4], float rsacc[4][4])
{
    const int tid  = threadIdx.x;
    const int lane = tid & 31;
    const int w    = tid >> 5;
    const int m_off = (w >> 2) * 64;
    const int n_off = (w & 3) * 32;
    uint32_t sb = smem_u32(smem);
    const uint32_t ONE2 = 0x3C003C00u;     // packed fp16 {1.0, 1.0}

    // ldmatrix lane-address components
    const uint32_t a_row  = (uint32_t)(lane & 15);
    const uint32_t a_koff = (uint32_t)((lane >> 4) & 1) * 16;
    const uint32_t b_row  = (uint32_t)(((lane >> 4) << 3) + (lane & 7));
    const uint32_t b_koff = (uint32_t)((lane >> 3) & 1) * 16;

    // prefetch stage 0
    {
        uint32_t st = sb;
        stage_tile(st,           A, lda, tid);
        stage_tile(st + T_BYTES, B, ldb, tid);
        CP_COMMIT();
    }

    for (int i = 0; i < nChunks; ++i) {
        if (i + 1 < nChunks) {
            uint32_t st = sb + ((i + 1) & 1) * STAGE_B;
            stage_tile(st,           A + (size_t)(i + 1) * 32, lda, tid);
            stage_tile(st + T_BYTES, B + (size_t)(i + 1) * 32, ldb, tid);
            CP_COMMIT();
            CP_WAIT(1);
        } else {
            CP_WAIT(0);
        }
        __syncthreads();

        uint32_t st = sb + (i & 1) * STAGE_B;
        #pragma unroll
        for (int k16 = 0; k16 < 2; ++k16) {
            uint32_t kb = k16 * 32;       // 16 fp16 = 32 bytes
            uint32_t bh[8];
            #pragma unroll
            for (int h = 0; h < 2; ++h) {
                uint32_t addr = st + T_BYTES + (uint32_t)(n_off + h*16 + b_row) * 80 + kb + b_koff;
                ldsm4(bh[h*4], bh[h*4+1], bh[h*4+2], bh[h*4+3], addr);
            }
            #pragma unroll
            for (int mf = 0; mf < 4; ++mf) {
                uint32_t addr = st + (uint32_t)(m_off + mf*16 + a_row) * 80 + kb + a_koff;
                uint32_t a0, a1, a2, a3;
                ldsm4(a0, a1, a2, a3, addr);
                if (RS) {
                    mma16816(rsacc[mf], a0, a1, a2, a3, ONE2, ONE2);   // Σ A
                }
                #pragma unroll
                for (int nf = 0; nf < 4; ++nf) {
                    mma16816(acc[mf*4 + nf], a0, a1, a2, a3, bh[nf*2], bh[nf*2+1]);
                }
            }
        }
        __syncthreads();
    }
}

// ---------------------------------------------------------------------------
// Fused convert kernel: x and W fp32 -> fp16 in one launch.
// Grid covers x (NX elements) then W (NW elements), 4 elements/thread.
// ---------------------------------------------------------------------------
#define NX (BB*SS*DIM)     // 8388608
#define NW (QKV3*DIM)      // 3145728

__global__ void __launch_bounds__(256) convert_kernel(const float* __restrict__ x,
                                                      const float* __restrict__ W) {
    int i = (blockIdx.x * 256 + threadIdx.x) * 4;
    if (i < NX) {
        float4 v = *(const float4*)(x + i);
        store_h2(g_xa, i,     v.x, v.y);
        store_h2(g_xa, i + 2, v.z, v.w);
    } else {
        int j = i - NX;
        float4 v = *(const float4*)(W + j);
        store_h2(g_wa, j,     v.x, v.y);
        store_h2(g_wa, j + 2, v.z, v.w);
    }
}

// ---------------------------------------------------------------------------
// QKV GEMM: [8192,3072] = x @ W^T + bias.
// Epilogue: Q, K, V all stored single fp16 (V row-major; transposed next).
// ---------------------------------------------------------------------------
__global__ void __launch_bounds__(256, 2) qkv_mma(const float* __restrict__ bias) {
    extern __shared__ __align__(128) char sm[];
    const int m0 = blockIdx.y * 128, n0 = blockIdx.x * 128;
    const int lane = threadIdx.x & 31, w = threadIdx.x >> 5;
    const int m_off = (w >> 2) * 64, n_off = (w & 3) * 32;

    float acc[16][4];
    #pragma unroll
    for (int i = 0; i < 16; ++i)
        #pragma unroll
        for (int j = 0; j < 4; ++j) acc[i][j] = 0.0f;
    float rs_dummy[4][4];

    gemm128<false>(g_xa + (size_t)m0 * DIM, DIM,
                   g_wa + (size_t)n0 * DIM, DIM,
                   DIM / 32, sm, acc, rs_dummy);

    #pragma unroll
    for (int mf = 0; mf < 4; ++mf) {
        #pragma unroll
        for (int nf = 0; nf < 4; ++nf) {
            float* c = acc[mf*4 + nf];
            int r  = m0 + m_off + mf*16 + (lane >> 2);
            int cg = n0 + n_off + nf*8 + ((lane & 3) << 1);
            float b0 = bias[cg], b1 = bias[cg + 1];
            float v0 = c[0] + b0, v1 = c[1] + b1;     // row r
            float v2 = c[2] + b0, v3 = c[3] + b1;     // row r+8
            if (cg < AD) {
                store_h2(g_qa, (size_t)r * AD + cg,       v0, v1);
                store_h2(g_qa, (size_t)(r + 8) * AD + cg, v2, v3);
            } else if (cg < 2*AD) {
                int ck = cg - AD;
                store_h2(g_ka, (size_t)r * AD + ck,       v0, v1);
                store_h2(g_ka, (size_t)(r + 8) * AD + ck, v2, v3);
            } else {
                int cv = cg - 2*AD;
                store_h2(g_va, (size_t)r * AD + cv,       v0, v1);
                store_h2(g_va, (size_t)(r + 8) * AD + cv, v2, v3);
            }
        }
    }
}

// ---------------------------------------------------------------------------
// V transpose: g_va [B,S,AD] fp16 -> g_vta [B,AD,S] fp16.
// smem rows padded to 34 halves (68B) -> conflict-free both phases.
// ---------------------------------------------------------------------------
__global__ void __launch_bounds__(256) vt_kernel() {
    __shared__ __half t[32][34];
    const int b = blockIdx.z;
    const int k0 = blockIdx.x * 32, n0 = blockIdx.y * 32;
    const int tx = threadIdx.x, ty = threadIdx.y;     // 32 x 8
    const __half* V = g_va + (size_t)b * SS * AD;
    #pragma unroll
    for (int j = 0; j < 4; ++j)
        t[ty + j * 8][tx] = V[(size_t)(k0 + ty + j * 8) * AD + n0 + tx];
    __syncthreads();
    #pragma unroll
    for (int j = 0; j < 4; ++j) {
        int n = n0 + ty + j * 8;
        int k = k0 + tx;
        g_vta[((size_t)b * AD + n) * SS + k] = t[tx][ty + j * 8];
    }
}

// ---------------------------------------------------------------------------
// Scores GEMM + fused exp: writes UNNORMALIZED e = exp(s/32) as fp16.
// Diagonal blocks mask j>i to exactly 0 (matches -inf-before-scale reference).
// ---------------------------------------------------------------------------
__global__ void __launch_bounds__(256, 2) scores_mma() {
    const int bx = blockIdx.x, by = blockIdx.y, b = blockIdx.z;
    if (bx > by) return;
    extern __shared__ __align__(128) char sm[];
    const int m0 = by * 128, n0 = bx * 128;
    const int lane = threadIdx.x & 31, w = threadIdx.x >> 5;
    const int m_off = (w >> 2) * 64, n_off = (w & 3) * 32;

    float acc[16][4];
    #pragma unroll
    for (int i = 0; i < 16; ++i)
        #pragma unroll
        for (int j = 0; j < 4; ++j) acc[i][j] = 0.0f;
    float rs_dummy[4][4];

    const size_t qo = ((size_t)b * SS + m0) * AD;
    const size_t ko = ((size_t)b * SS + n0) * AD;
    gemm128<false>(g_qa + qo, AD, g_ka + ko, AD, AD / 32, sm, acc, rs_dummy);

    __half* pa = g_pa + (size_t)b * SS * SS;
    const float inv = 1.0f / 32.0f;
    const bool diag = (bx == by);
    #pragma unroll
    for (int mf = 0; mf < 4; ++mf) {
        #pragma unroll
        for (int nf = 0; nf < 4; ++nf) {
            float* c = acc[mf*4 + nf];
            int r  = m0 + m_off + mf*16 + (lane >> 2);
            int cg = n0 + n_off + nf*8 + ((lane & 3) << 1);
            float e0 = expf(c[0] * inv), e1 = expf(c[1] * inv);
            float e2 = expf(c[2] * inv), e3 = expf(c[3] * inv);
            if (diag) {
                if (cg     > r)     e0 = 0.0f;
                if (cg + 1 > r)     e1 = 0.0f;
                if (cg     > r + 8) e2 = 0.0f;
                if (cg + 1 > r + 8) e3 = 0.0f;
            }
            store_h2(pa, (size_t)r * SS + cg,       e0, e1);
            store_h2(pa, (size_t)(r + 8) * SS + cg, e2, e3);
        }
    }
}

// ---------------------------------------------------------------------------
// PV GEMM: y = (E @ V) / rowsum(E), K truncated at causal boundary.
// Heavy-first scheduling: by remapped so 128-chunk CTAs launch in wave 1.
// Row sums via ones-vector MMA on the SAME fp16 E used in the numerator.
// ---------------------------------------------------------------------------
__global__ void __launch_bounds__(256, 2) pv_mma(float* __restrict__ y) {
    extern __shared__ __align__(128) char sm[];
    const int b = blockIdx.z;
    const int byr = (int)gridDim.y - 1 - (int)blockIdx.y;   // heavy tiles first
    const int m0 = byr * 128, n0 = blockIdx.x * 128;
    const int lane = threadIdx.x & 31, w = threadIdx.x >> 5;
    const int m_off = (w >> 2) * 64, n_off = (w & 3) * 32;

    float acc[16][4];
    #pragma unroll
    for (int i = 0; i < 16; ++i)
        #pragma unroll
        for (int j = 0; j < 4; ++j) acc[i][j] = 0.0f;
    float rs[4][4];
    #pragma unroll
    for (int i = 0; i < 4; ++i)
        #pragma unroll
        for (int j = 0; j < 4; ++j) rs[i][j] = 0.0f;

    const size_t po = ((size_t)b * SS + m0) * SS;
    const size_t vo = ((size_t)b * AD + n0) * SS;
    gemm128<true>(g_pa + po, SS, g_vta + vo, SS,
                  (byr + 1) * 4, sm, acc, rs);

    #pragma unroll
    for (int mf = 0; mf < 4; ++mf) {
        const float i0 = 1.0f / rs[mf][0];     // row r   sum
        const float i1 = 1.0f / rs[mf][2];     // row r+8 sum
        #pragma unroll
        for (int nf = 0; nf < 4; ++nf) {
            float* c = acc[mf*4 + nf];
            int r  = m0 + m_off + mf*16 + (lane >> 2);
            int cg = n0 + n_off + nf*8 + ((lane & 3) << 1);
            *(float2*)(y + ((size_t)b * SS + r) * AD + cg)     = make_float2(c[0] * i0, c[1] * i0);
            *(float2*)(y + ((size_t)b * SS + r + 8) * AD + cg) = make_float2(c[2] * i1, c[3] * i1);
        }
    }
}

// ---------------------------------------------------------------------------
extern "C" void kernel_launch(void* const* d_in, const int* in_sizes, int n_in,
                              void* d_out, int out_size)
{
    const float* x    = (const float*)d_in[0];   // [B,S,DIM]
    const float* W    = (const float*)d_in[1];   // [3*AD, DIM]
    const float* bias = (const float*)d_in[2];   // [3*AD]
    float* y = (float*)d_out;                    // [B,S,AD]

    cudaFuncSetAttribute(qkv_mma,    cudaFuncAttributeMaxDynamicSharedMemorySize, SMEM_TOTAL);
    cudaFuncSetAttribute(scores_mma, cudaFuncAttributeMaxDynamicSharedMemorySize, SMEM_TOTAL);
    cudaFuncSetAttribute(pv_mma,     cudaFuncAttributeMaxDynamicSharedMemorySize, SMEM_TOTAL);

    convert_kernel<<<(NX + NW) / 1024, 256>>>(x, W);
    qkv_mma   <<<dim3(QKV3/128, (BB*SS)/128), 256, SMEM_TOTAL>>>(bias);
    vt_kernel <<<dim3(SS/32, AD/32, BB), dim3(32, 8)>>>();
    scores_mma<<<dim3(SS/128, SS/128, BB), 256, SMEM_TOTAL>>>();
    pv_mma    <<<dim3(AD/128, SS/128, BB), 256, SMEM_TOTAL>>>(y);
}